// round 2
// baseline (speedup 1.0000x reference)
#include <cuda_runtime.h>
#include <cuda_bf16.h>
#include <math.h>

#define NN 100000
#define NE 1600000
#define NF 512
#define FD 128
#define NC 10

// ---------------- device scratch (static, no allocs) ----------------
__device__ __align__(16) float g_A[NN * FD];
__device__ __align__(16) float g_B[NN * FD];
__device__ __align__(16) float g_C[NN * FD];
__device__ __align__(16) float g_D[NN * FD];
__device__ __align__(16) float g_E[NN * FD];
__device__ __align__(16) float g_F[NN * NC];
__device__ float g_deg1[NN], g_degh[NN];
__device__ float g_inv1[NN], g_dis1[NN], g_invh[NN], g_dish[NN];
__device__ float g_w1[NE], g_wh[NE];

// ---------------- helpers ----------------
__device__ __forceinline__ void red_add_v4(float* addr, float4 v) {
    asm volatile("red.global.add.v4.f32 [%0], {%1,%2,%3,%4};"
                 :: "l"(addr), "f"(v.x), "f"(v.y), "f"(v.z), "f"(v.w)
                 : "memory");
}

// ---------------- degree / edge weight precompute ----------------
__global__ void k_set_ones(float* a, float* b, int n) {
    int i = blockIdx.x * blockDim.x + threadIdx.x;
    if (i < n) { a[i] = 1.0f; b[i] = 1.0f; }
}

__global__ void k_count(const int* __restrict__ d1, const int* __restrict__ dh,
                        float* deg1, float* degh, int e) {
    int i = blockIdx.x * blockDim.x + threadIdx.x;
    if (i < e) {
        atomicAdd(&deg1[d1[i]], 1.0f);
        atomicAdd(&degh[dh[i]], 1.0f);
    }
}

__global__ void k_finish(const float* __restrict__ deg1, const float* __restrict__ degh,
                         float* inv1, float* dis1, float* invh, float* dish, int n) {
    int i = blockIdx.x * blockDim.x + threadIdx.x;
    if (i < n) {
        float d = deg1[i];
        inv1[i] = 1.0f / d;
        dis1[i] = rsqrtf(d);
        float dh = degh[i];
        invh[i] = 1.0f / dh;
        dish[i] = rsqrtf(dh);
    }
}

__global__ void k_edgew(const int* __restrict__ s, const int* __restrict__ d,
                        const float* __restrict__ dis, float* w, int e) {
    int i = blockIdx.x * blockDim.x + threadIdx.x;
    if (i < e) w[i] = dis[s[i]] * dis[d[i]];
}

// ---------------- GCN aggregation ----------------
// out[i] = in[i] * inv[i] + bias   (self-loop term + bias)
__global__ void k_conv_init(float4* __restrict__ out, const float4* __restrict__ in,
                            const float* __restrict__ inv, const float* __restrict__ bias, int n) {
    int idx = blockIdx.x * blockDim.x + threadIdx.x;
    if (idx >= n * 32) return;
    int i = idx >> 5, q = idx & 31;
    float iv = inv[i];
    float4 v = in[idx];
    float4 b = ((const float4*)bias)[q];
    out[idx] = make_float4(fmaf(v.x, iv, b.x), fmaf(v.y, iv, b.y),
                           fmaf(v.z, iv, b.z), fmaf(v.w, iv, b.w));
}

// warp per edge: out[dst] += in[src] * w[e]
__global__ void k_conv_edge(float* __restrict__ out, const float* __restrict__ in,
                            const int* __restrict__ src, const int* __restrict__ dst,
                            const float* __restrict__ we, int e) {
    int gid = blockIdx.x * blockDim.x + threadIdx.x;
    int eid = gid >> 5, lane = gid & 31;
    if (eid >= e) return;
    int s = __ldg(&src[eid]);
    int d = __ldg(&dst[eid]);
    float w = __ldg(&we[eid]);
    float4 v = __ldg((const float4*)in + (size_t)s * 32 + lane);
    float4 m = make_float4(v.x * w, v.y * w, v.z * w, v.w * w);
    red_add_v4(out + (size_t)d * FD + lane * 4, m);
}

__global__ void k_gather(float4* __restrict__ out, const float4* __restrict__ in,
                         const int* __restrict__ perm, int n) {
    int idx = blockIdx.x * blockDim.x + threadIdx.x;
    if (idx >= n * 32) return;
    int i = idx >> 5, q = idx & 31;
    out[idx] = in[(size_t)perm[i] * 32 + q];
}

// ---------------- GEMM: C[n,128] = act(A)[n,K] @ W[K,128] (+bias)(+relu out) ------
// RELUIN applies relu to A elements on load (idempotent fusion of prior activation).
template <int K, bool BIAS, bool RELUOUT, bool RELUIN>
__global__ void __launch_bounds__(128) k_gemm(const float* __restrict__ A,
                                              const float* __restrict__ W,
                                              const float* __restrict__ bias,
                                              float* __restrict__ C, int n) {
    constexpr int BM = 64, BN = 128, BK = 32, TM = 8, TN = 8;
    __shared__ float As[BK][BM];
    __shared__ float Bs[BK][BN];
    int tid = threadIdx.x;
    int m0 = blockIdx.x * BM;
    int trow = tid / 16;   // 0..7
    int tcol = tid % 16;   // 0..15
    float acc[TM][TN] = {};

    for (int k0 = 0; k0 < K; k0 += BK) {
        // A tile: 64x32 = 512 float4, 4 per thread; stored transposed
        #pragma unroll
        for (int i = 0; i < 4; i++) {
            int idx = tid + i * 128;
            int row = idx >> 3;
            int kv  = idx & 7;
            float4 v = make_float4(0.f, 0.f, 0.f, 0.f);
            int m = m0 + row;
            if (m < n) v = *(const float4*)&A[(size_t)m * K + k0 + kv * 4];
            if (RELUIN) {
                v.x = fmaxf(v.x, 0.f); v.y = fmaxf(v.y, 0.f);
                v.z = fmaxf(v.z, 0.f); v.w = fmaxf(v.w, 0.f);
            }
            As[kv * 4 + 0][row] = v.x;
            As[kv * 4 + 1][row] = v.y;
            As[kv * 4 + 2][row] = v.z;
            As[kv * 4 + 3][row] = v.w;
        }
        // W tile: 32x128 = 1024 float4, 8 per thread
        #pragma unroll
        for (int i = 0; i < 8; i++) {
            int idx = tid + i * 128;
            int row = idx >> 5;
            int cv  = idx & 31;
            *(float4*)&Bs[row][cv * 4] = *(const float4*)&W[(size_t)(k0 + row) * BN + cv * 4];
        }
        __syncthreads();
        #pragma unroll
        for (int kk = 0; kk < BK; kk++) {
            float a[TM], b[TN];
            #pragma unroll
            for (int r = 0; r < TM; r++) a[r] = As[kk][trow * TM + r];
            #pragma unroll
            for (int c = 0; c < TN; c++) b[c] = Bs[kk][tcol * TN + c];
            #pragma unroll
            for (int r = 0; r < TM; r++)
                #pragma unroll
                for (int c = 0; c < TN; c++)
                    acc[r][c] = fmaf(a[r], b[c], acc[r][c]);
        }
        __syncthreads();
    }

    float bf[TN];
    #pragma unroll
    for (int c = 0; c < TN; c++) bf[c] = BIAS ? bias[tcol * TN + c] : 0.0f;

    #pragma unroll
    for (int r = 0; r < TM; r++) {
        int m = m0 + trow * TM + r;
        if (m < n) {
            float o[TN];
            #pragma unroll
            for (int c = 0; c < TN; c++) {
                float v = acc[r][c] + bf[c];
                o[c] = RELUOUT ? fmaxf(v, 0.0f) : v;
            }
            float* crow = &C[(size_t)m * BN + tcol * TN];
            *(float4*)&crow[0] = make_float4(o[0], o[1], o[2], o[3]);
            *(float4*)&crow[4] = make_float4(o[4], o[5], o[6], o[7]);
        }
    }
}

// ---------------- bilinear score: out[i,col] = sigmoid(dot(u[i], v[i])) ----------------
__global__ void k_rowdot(float* __restrict__ out, const float4* __restrict__ u,
                         const float4* __restrict__ v, int col, int n) {
    int gid = blockIdx.x * blockDim.x + threadIdx.x;
    int i = gid >> 5, lane = gid & 31;
    if (i >= n) return;
    float4 a = u[(size_t)i * 32 + lane];
    float4 b = v[(size_t)i * 32 + lane];
    float s = a.x * b.x + a.y * b.y + a.z * b.z + a.w * b.w;
    #pragma unroll
    for (int off = 16; off > 0; off >>= 1)
        s += __shfl_down_sync(0xffffffffu, s, off);
    if (lane == 0) out[(size_t)i * 12 + col] = 1.0f / (1.0f + expf(-s));
}

// ---------------- classifier: F[n,10] = relu(D)[n,128] @ Wc[128,10] ----------------
__global__ void k_gemm_wc(float* __restrict__ F, const float* __restrict__ D,
                          const float* __restrict__ Wc, int n) {
    __shared__ float wcs[FD * NC];
    for (int t = threadIdx.x; t < FD * NC; t += blockDim.x) wcs[t] = Wc[t];
    __syncthreads();
    int gid = blockIdx.x * blockDim.x + threadIdx.x;
    if (gid >= n * NC) return;
    int i = gid / NC, j = gid % NC;
    const float* drow = &D[(size_t)i * FD];
    float s = 0.0f;
    #pragma unroll
    for (int k = 0; k < FD; k++)
        s = fmaf(fmaxf(__ldg(&drow[k]), 0.0f), wcs[k * NC + j], s);
    F[gid] = s;
}

__global__ void k_out_init(float* __restrict__ out, const float* __restrict__ F,
                           const float* __restrict__ inv1, const float* __restrict__ bc, int n) {
    int gid = blockIdx.x * blockDim.x + threadIdx.x;
    if (gid >= n * NC) return;
    int i = gid / NC, j = gid % NC;
    out[(size_t)i * 12 + j] = fmaf(F[gid], inv1[i], bc[j]);
}

__global__ void k_out_edge(float* __restrict__ out, const float* __restrict__ F,
                           const int* __restrict__ src, const int* __restrict__ dst,
                           const float* __restrict__ we, int e) {
    int i = blockIdx.x * blockDim.x + threadIdx.x;
    if (i >= e) return;
    int s = src[i], d = dst[i];
    float w = we[i];
    const float* fr = &F[(size_t)s * NC];
    float* orow = &out[(size_t)d * 12];
    #pragma unroll
    for (int j = 0; j < NC; j++) atomicAdd(&orow[j], fr[j] * w);
}

// ---------------- launch ----------------
static inline int nb(long total, int tpb) { return (int)((total + tpb - 1) / tpb); }

extern "C" void kernel_launch(void* const* d_in, const int* in_sizes, int n_in,
                              void* d_out, int out_size) {
    const float* x    = (const float*)d_in[0];
    const int*   e1   = (const int*)d_in[1];
    const int*   eh   = (const int*)d_in[2];
    const int*   perm = (const int*)d_in[4];
    const float* W1 = (const float*)d_in[5];
    const float* b1 = (const float*)d_in[6];
    const float* W2 = (const float*)d_in[7];
    const float* b2 = (const float*)d_in[8];
    const float* W3 = (const float*)d_in[9];
    const float* b3 = (const float*)d_in[10];
    const float* M1 = (const float*)d_in[11];
    const float* mb1 = (const float*)d_in[12];
    const float* M2 = (const float*)d_in[13];
    const float* mb2 = (const float*)d_in[14];
    const float* Wc = (const float*)d_in[15];
    const float* bc = (const float*)d_in[16];
    const float* Wd = (const float*)d_in[17];
    float* out = (float*)d_out;

    const int* src1 = e1;       const int* dst1 = e1 + NE;
    const int* srch = eh;       const int* dsth = eh + NE;

    float *A, *B, *C, *D, *Ebuf, *F;
    float *deg1, *degh, *inv1, *dis1, *invh, *dish, *w1, *wh;
    cudaGetSymbolAddress((void**)&A, g_A);
    cudaGetSymbolAddress((void**)&B, g_B);
    cudaGetSymbolAddress((void**)&C, g_C);
    cudaGetSymbolAddress((void**)&D, g_D);
    cudaGetSymbolAddress((void**)&Ebuf, g_E);
    cudaGetSymbolAddress((void**)&F, g_F);
    cudaGetSymbolAddress((void**)&deg1, g_deg1);
    cudaGetSymbolAddress((void**)&degh, g_degh);
    cudaGetSymbolAddress((void**)&inv1, g_inv1);
    cudaGetSymbolAddress((void**)&dis1, g_dis1);
    cudaGetSymbolAddress((void**)&invh, g_invh);
    cudaGetSymbolAddress((void**)&dish, g_dish);
    cudaGetSymbolAddress((void**)&w1, g_w1);
    cudaGetSymbolAddress((void**)&wh, g_wh);

    const int T = 256;

    // degrees + edge weights
    k_set_ones<<<nb(NN, T), T>>>(deg1, degh, NN);
    k_count<<<nb(NE, T), T>>>(dst1, dsth, deg1, degh, NE);
    k_finish<<<nb(NN, T), T>>>(deg1, degh, inv1, dis1, invh, dish, NN);
    k_edgew<<<nb(NE, T), T>>>(src1, dst1, dis1, w1, NE);
    k_edgew<<<nb(NE, T), T>>>(srch, dsth, dish, wh, NE);

    #define CONV(OUT, IN, INV, BIAS, SRC, DST, WE)                                        \
        k_conv_init<<<nb((long)NN * 32, T), T>>>((float4*)(OUT), (const float4*)(IN),     \
                                                 (INV), (BIAS), NN);                      \
        k_conv_edge<<<nb((long)NE * 32, T), T>>>((OUT), (IN), (SRC), (DST), (WE), NE);

    // h1 = x @ W1
    k_gemm<NF, false, false, false><<<nb(NN, 64), 128>>>(x, W1, nullptr, A, NN);

    // encoder1 layer1: B = conv(h1)  (relu deferred to consumer)
    CONV(B, A, inv1, b1, src1, dst1, w1);
    // layer2: C = relu(B) @ W2 ; D = conv(C)  => D is pre-relu embed1
    k_gemm<FD, false, false, true><<<nb(NN, 64), 128>>>(B, W2, nullptr, C, NN);
    CONV(D, C, inv1, b2, src1, dst1, w1);              // relu(D) = embed1

    // encoder3 MLP: embed3 = relu(relu(D)@M1+mb1)@M2+mb2
    k_gemm<FD, true, false, true ><<<nb(NN, 64), 128>>>(D, M1, mb1, B, NN);
    k_gemm<FD, true, false, true ><<<nb(NN, 64), 128>>>(B, M2, mb2, C, NN);  // C = embed3

    // encoder2: embed2 = conv_hop(relu(D) @ W3)
    k_gemm<FD, false, false, true><<<nb(NN, 64), 128>>>(D, W3, nullptr, B, NN);
    CONV(Ebuf, B, invh, b3, srch, dsth, wh);           // Ebuf = embed2

    // u = embed3 @ Wd0 ; score = sigmoid(<u, embed2>)
    k_gemm<FD, false, false, false><<<nb(NN, 64), 128>>>(C, Wd, nullptr, B, NN);  // B = u (keep)
    k_rowdot<<<nb((long)NN * 32, T), T>>>(out, (const float4*)B, (const float4*)Ebuf, 10, NN);

    // permuted path: h1b = h1[perm]  (x[perm]@W1 == (x@W1)[perm])
    k_gather<<<nb((long)NN * 32, T), T>>>((float4*)Ebuf, (const float4*)A, perm, NN);
    CONV(A, Ebuf, inv1, b1, src1, dst1, w1);
    k_gemm<FD, false, false, true><<<nb(NN, 64), 128>>>(A, W2, nullptr, Ebuf, NN);
    CONV(A, Ebuf, inv1, b2, src1, dst1, w1);           // relu(A) = embed1_bad
    k_gemm<FD, false, false, true><<<nb(NN, 64), 128>>>(A, W3, nullptr, Ebuf, NN);
    CONV(A, Ebuf, invh, b3, srch, dsth, wh);           // A = embed2_bad
    k_rowdot<<<nb((long)NN * 32, T), T>>>(out, (const float4*)B, (const float4*)A, 11, NN);

    // classifier: out[:,0:10] = conv(relu(D) @ Wc) + bc
    k_gemm_wc<<<nb((long)NN * NC, T), T>>>(F, D, Wc, NN);
    k_out_init<<<nb((long)NN * NC, T), T>>>(out, F, inv1, bc, NN);
    k_out_edge<<<nb(NE, T), T>>>(out, F, src1, dst1, w1, NE);

    #undef CONV
}

// round 3
// speedup vs baseline: 1.5175x; 1.5175x over previous
#include <cuda_runtime.h>
#include <cuda_bf16.h>
#include <math.h>

#define NN 100000
#define NE 1600000
#define NF 512
#define FD 128
#define NC 10

#define SCAN_B 512
#define SCAN_NBLK ((NN + SCAN_B - 1) / SCAN_B)

// ---------------- device scratch (static, no allocs) ----------------
__device__ __align__(16) float g_A[NN * FD];
__device__ __align__(16) float g_B[NN * FD];
__device__ __align__(16) float g_C[NN * FD];
__device__ __align__(16) float g_D[NN * FD];
__device__ __align__(16) float g_E[NN * FD];
__device__ __align__(16) float g_F[NN * NC];
__device__ int   g_cnt1[NN], g_cnth[NN];
__device__ int   g_cur1[NN], g_curh[NN];
__device__ int   g_start1[NN + 1], g_starth[NN + 1];
__device__ int   g_part[SCAN_NBLK];
__device__ float g_inv1[NN], g_dis1[NN], g_invh[NN], g_dish[NN];
__device__ int   g_csrc1[NE], g_csrch[NE];
__device__ float g_csw1[NE], g_cswh[NE];

// ---------------- degree / CSR build ----------------
__global__ void k_zero(int* a, int* b, int* c, int* d, int n) {
    int i = blockIdx.x * blockDim.x + threadIdx.x;
    if (i < n) { a[i] = 0; b[i] = 0; c[i] = 0; d[i] = 0; }
}

__global__ void k_count(const int* __restrict__ d1, const int* __restrict__ dh,
                        int* cnt1, int* cnth, int e) {
    int i = blockIdx.x * blockDim.x + threadIdx.x;
    if (i < e) {
        atomicAdd(&cnt1[d1[i]], 1);
        atomicAdd(&cnth[dh[i]], 1);
    }
}

__global__ void k_finish(const int* __restrict__ cnt1, const int* __restrict__ cnth,
                         float* inv1, float* dis1, float* invh, float* dish, int n) {
    int i = blockIdx.x * blockDim.x + threadIdx.x;
    if (i < n) {
        float d = (float)cnt1[i] + 1.0f;
        inv1[i] = 1.0f / d;
        dis1[i] = rsqrtf(d);
        float dh = (float)cnth[i] + 1.0f;
        invh[i] = 1.0f / dh;
        dish[i] = rsqrtf(dh);
    }
}

// scan stage 1: per-block sums
__global__ void k_scan1(const int* __restrict__ cnt, int* part, int n) {
    __shared__ int sh[SCAN_B];
    int i = blockIdx.x * SCAN_B + threadIdx.x;
    sh[threadIdx.x] = (i < n) ? cnt[i] : 0;
    __syncthreads();
    for (int off = SCAN_B / 2; off > 0; off >>= 1) {
        if (threadIdx.x < off) sh[threadIdx.x] += sh[threadIdx.x + off];
        __syncthreads();
    }
    if (threadIdx.x == 0) part[blockIdx.x] = sh[0];
}

// scan stage 2: serial exclusive scan of block partials (tiny)
__global__ void k_scan2(int* part, int nblk) {
    if (threadIdx.x == 0 && blockIdx.x == 0) {
        int run = 0;
        for (int b = 0; b < nblk; b++) { int v = part[b]; part[b] = run; run += v; }
    }
}

// scan stage 3: intra-block exclusive scan + partial offset
__global__ void k_scan3(const int* __restrict__ cnt, const int* __restrict__ part,
                        int* start, int n) {
    __shared__ int sh[SCAN_B];
    int i = blockIdx.x * SCAN_B + threadIdx.x;
    int v = (i < n) ? cnt[i] : 0;
    sh[threadIdx.x] = v;
    __syncthreads();
    // Hillis-Steele inclusive scan
    for (int off = 1; off < SCAN_B; off <<= 1) {
        int t = (threadIdx.x >= off) ? sh[threadIdx.x - off] : 0;
        __syncthreads();
        sh[threadIdx.x] += t;
        __syncthreads();
    }
    if (i < n) {
        int excl = sh[threadIdx.x] - v + part[blockIdx.x];
        start[i] = excl;
        if (i == n - 1) start[n] = excl + v;
    }
}

__global__ void k_fill(const int* __restrict__ src, const int* __restrict__ dst,
                       const int* __restrict__ start, int* cur,
                       const float* __restrict__ dis,
                       int* csrc, float* csw, int e) {
    int i = blockIdx.x * blockDim.x + threadIdx.x;
    if (i >= e) return;
    int s = src[i], d = dst[i];
    int pos = start[d] + atomicAdd(&cur[d], 1);
    csrc[pos] = s;
    csw[pos] = dis[s] * dis[d];
}

// ---------------- CSR GCN conv: warp per node, 128 features ----------------
__global__ void __launch_bounds__(256) k_conv_csr(
    float4* __restrict__ out, const float4* __restrict__ in,
    const int* __restrict__ start, const int* __restrict__ csrc,
    const float* __restrict__ csw, const float* __restrict__ inv,
    const float* __restrict__ bias) {
    int gid = blockIdx.x * blockDim.x + threadIdx.x;
    int node = gid >> 5, lane = gid & 31;
    if (node >= NN) return;
    int e0 = start[node], e1 = start[node + 1];
    float iv = inv[node];
    float4 b = ((const float4*)bias)[lane];
    float4 v = in[(size_t)node * 32 + lane];
    float ax = fmaf(v.x, iv, b.x), ay = fmaf(v.y, iv, b.y);
    float az = fmaf(v.z, iv, b.z), aw = fmaf(v.w, iv, b.w);
    #pragma unroll 4
    for (int e = e0; e < e1; e++) {
        int s = __ldg(&csrc[e]);
        float w = __ldg(&csw[e]);
        float4 u = __ldg(in + (size_t)s * 32 + lane);
        ax = fmaf(u.x, w, ax); ay = fmaf(u.y, w, ay);
        az = fmaf(u.z, w, az); aw = fmaf(u.w, w, aw);
    }
    out[(size_t)node * 32 + lane] = make_float4(ax, ay, az, aw);
}

// classifier conv: warp per node, 10 features, writes out[:,0:10]
__global__ void __launch_bounds__(256) k_conv_csr_nc(
    float* __restrict__ out, const float* __restrict__ F,
    const int* __restrict__ start, const int* __restrict__ csrc,
    const float* __restrict__ csw, const float* __restrict__ inv,
    const float* __restrict__ bc) {
    int gid = blockIdx.x * blockDim.x + threadIdx.x;
    int node = gid >> 5, lane = gid & 31;
    if (node >= NN) return;
    int e0 = start[node], e1 = start[node + 1];
    float acc = 0.0f;
    if (lane < NC)
        acc = fmaf(F[(size_t)node * NC + lane], inv[node], bc[lane]);
    #pragma unroll 4
    for (int e = e0; e < e1; e++) {
        int s = __ldg(&csrc[e]);
        float w = __ldg(&csw[e]);
        if (lane < NC) acc = fmaf(__ldg(&F[(size_t)s * NC + lane]), w, acc);
    }
    if (lane < NC) out[(size_t)node * 12 + lane] = acc;
}

__global__ void k_gather(float4* __restrict__ out, const float4* __restrict__ in,
                         const int* __restrict__ perm, int n) {
    int idx = blockIdx.x * blockDim.x + threadIdx.x;
    if (idx >= n * 32) return;
    int i = idx >> 5, q = idx & 31;
    out[idx] = in[(size_t)perm[i] * 32 + q];
}

// ---------------- GEMM: C[n,128] = act(A)[n,K] @ W[K,128] (+bias) ------
template <int K, bool BIAS, bool RELUIN>
__global__ void __launch_bounds__(128) k_gemm(const float* __restrict__ A,
                                              const float* __restrict__ W,
                                              const float* __restrict__ bias,
                                              float* __restrict__ C, int n) {
    constexpr int BM = 64, BN = 128, BK = 32, TM = 8, TN = 8;
    __shared__ float As[BK][BM];
    __shared__ float Bs[BK][BN];
    int tid = threadIdx.x;
    int m0 = blockIdx.x * BM;
    int trow = tid / 16;
    int tcol = tid % 16;
    float acc[TM][TN] = {};

    for (int k0 = 0; k0 < K; k0 += BK) {
        #pragma unroll
        for (int i = 0; i < 4; i++) {
            int idx = tid + i * 128;
            int row = idx >> 3;
            int kv  = idx & 7;
            float4 v = make_float4(0.f, 0.f, 0.f, 0.f);
            int m = m0 + row;
            if (m < n) v = *(const float4*)&A[(size_t)m * K + k0 + kv * 4];
            if (RELUIN) {
                v.x = fmaxf(v.x, 0.f); v.y = fmaxf(v.y, 0.f);
                v.z = fmaxf(v.z, 0.f); v.w = fmaxf(v.w, 0.f);
            }
            As[kv * 4 + 0][row] = v.x;
            As[kv * 4 + 1][row] = v.y;
            As[kv * 4 + 2][row] = v.z;
            As[kv * 4 + 3][row] = v.w;
        }
        #pragma unroll
        for (int i = 0; i < 8; i++) {
            int idx = tid + i * 128;
            int row = idx >> 5;
            int cv  = idx & 31;
            *(float4*)&Bs[row][cv * 4] = *(const float4*)&W[(size_t)(k0 + row) * BN + cv * 4];
        }
        __syncthreads();
        #pragma unroll
        for (int kk = 0; kk < BK; kk++) {
            float a[TM], b[TN];
            #pragma unroll
            for (int r = 0; r < TM; r++) a[r] = As[kk][trow * TM + r];
            #pragma unroll
            for (int c = 0; c < TN; c++) b[c] = Bs[kk][tcol * TN + c];
            #pragma unroll
            for (int r = 0; r < TM; r++)
                #pragma unroll
                for (int c = 0; c < TN; c++)
                    acc[r][c] = fmaf(a[r], b[c], acc[r][c]);
        }
        __syncthreads();
    }

    float bf[TN];
    #pragma unroll
    for (int c = 0; c < TN; c++) bf[c] = BIAS ? bias[tcol * TN + c] : 0.0f;

    #pragma unroll
    for (int r = 0; r < TM; r++) {
        int m = m0 + trow * TM + r;
        if (m < n) {
            float o[TN];
            #pragma unroll
            for (int c = 0; c < TN; c++) o[c] = acc[r][c] + bf[c];
            float* crow = &C[(size_t)m * BN + tcol * TN];
            *(float4*)&crow[0] = make_float4(o[0], o[1], o[2], o[3]);
            *(float4*)&crow[4] = make_float4(o[4], o[5], o[6], o[7]);
        }
    }
}

// ---------------- bilinear score ----------------
__global__ void k_rowdot(float* __restrict__ out, const float4* __restrict__ u,
                         const float4* __restrict__ v, int col, int n) {
    int gid = blockIdx.x * blockDim.x + threadIdx.x;
    int i = gid >> 5, lane = gid & 31;
    if (i >= n) return;
    float4 a = u[(size_t)i * 32 + lane];
    float4 b = v[(size_t)i * 32 + lane];
    float s = a.x * b.x + a.y * b.y + a.z * b.z + a.w * b.w;
    #pragma unroll
    for (int off = 16; off > 0; off >>= 1)
        s += __shfl_down_sync(0xffffffffu, s, off);
    if (lane == 0) out[(size_t)i * 12 + col] = 1.0f / (1.0f + expf(-s));
}

// ---------------- classifier pre-GEMM: F[n,10] = relu(D) @ Wc ----------------
__global__ void k_gemm_wc(float* __restrict__ F, const float* __restrict__ D,
                          const float* __restrict__ Wc, int n) {
    __shared__ float wcs[FD * NC];
    for (int t = threadIdx.x; t < FD * NC; t += blockDim.x) wcs[t] = Wc[t];
    __syncthreads();
    int gid = blockIdx.x * blockDim.x + threadIdx.x;
    if (gid >= n * NC) return;
    int i = gid / NC, j = gid % NC;
    const float* drow = &D[(size_t)i * FD];
    float s = 0.0f;
    #pragma unroll
    for (int k = 0; k < FD; k++)
        s = fmaf(fmaxf(__ldg(&drow[k]), 0.0f), wcs[k * NC + j], s);
    F[gid] = s;
}

// ---------------- launch ----------------
static inline int nb(long total, int tpb) { return (int)((total + tpb - 1) / tpb); }

extern "C" void kernel_launch(void* const* d_in, const int* in_sizes, int n_in,
                              void* d_out, int out_size) {
    const float* x    = (const float*)d_in[0];
    const int*   e1   = (const int*)d_in[1];
    const int*   eh   = (const int*)d_in[2];
    const int*   perm = (const int*)d_in[4];
    const float* W1 = (const float*)d_in[5];
    const float* b1 = (const float*)d_in[6];
    const float* W2 = (const float*)d_in[7];
    const float* b2 = (const float*)d_in[8];
    const float* W3 = (const float*)d_in[9];
    const float* b3 = (const float*)d_in[10];
    const float* M1 = (const float*)d_in[11];
    const float* mb1 = (const float*)d_in[12];
    const float* M2 = (const float*)d_in[13];
    const float* mb2 = (const float*)d_in[14];
    const float* Wc = (const float*)d_in[15];
    const float* bc = (const float*)d_in[16];
    const float* Wd = (const float*)d_in[17];
    float* out = (float*)d_out;

    const int* src1 = e1;       const int* dst1 = e1 + NE;
    const int* srch = eh;       const int* dsth = eh + NE;

    float *A, *B, *C, *D, *Ebuf, *F;
    float *inv1, *dis1, *invh, *dish, *csw1, *cswh;
    int *cnt1, *cnth, *cur1, *curh, *start1, *starth, *part, *csrc1, *csrch;
    cudaGetSymbolAddress((void**)&A, g_A);
    cudaGetSymbolAddress((void**)&B, g_B);
    cudaGetSymbolAddress((void**)&C, g_C);
    cudaGetSymbolAddress((void**)&D, g_D);
    cudaGetSymbolAddress((void**)&Ebuf, g_E);
    cudaGetSymbolAddress((void**)&F, g_F);
    cudaGetSymbolAddress((void**)&cnt1, g_cnt1);
    cudaGetSymbolAddress((void**)&cnth, g_cnth);
    cudaGetSymbolAddress((void**)&cur1, g_cur1);
    cudaGetSymbolAddress((void**)&curh, g_curh);
    cudaGetSymbolAddress((void**)&start1, g_start1);
    cudaGetSymbolAddress((void**)&starth, g_starth);
    cudaGetSymbolAddress((void**)&part, g_part);
    cudaGetSymbolAddress((void**)&inv1, g_inv1);
    cudaGetSymbolAddress((void**)&dis1, g_dis1);
    cudaGetSymbolAddress((void**)&invh, g_invh);
    cudaGetSymbolAddress((void**)&dish, g_dish);
    cudaGetSymbolAddress((void**)&csrc1, g_csrc1);
    cudaGetSymbolAddress((void**)&csrch, g_csrch);
    cudaGetSymbolAddress((void**)&csw1, g_csw1);
    cudaGetSymbolAddress((void**)&cswh, g_cswh);

    const int T = 256;

    // ---- CSR build (both graphs) ----
    k_zero<<<nb(NN, T), T>>>(cnt1, cnth, cur1, curh, NN);
    k_count<<<nb(NE, T), T>>>(dst1, dsth, cnt1, cnth, NE);
    k_finish<<<nb(NN, T), T>>>(cnt1, cnth, inv1, dis1, invh, dish, NN);
    k_scan1<<<SCAN_NBLK, SCAN_B>>>(cnt1, part, NN);
    k_scan2<<<1, 32>>>(part, SCAN_NBLK);
    k_scan3<<<SCAN_NBLK, SCAN_B>>>(cnt1, part, start1, NN);
    k_scan1<<<SCAN_NBLK, SCAN_B>>>(cnth, part, NN);
    k_scan2<<<1, 32>>>(part, SCAN_NBLK);
    k_scan3<<<SCAN_NBLK, SCAN_B>>>(cnth, part, starth, NN);
    k_fill<<<nb(NE, T), T>>>(src1, dst1, start1, cur1, dis1, csrc1, csw1, NE);
    k_fill<<<nb(NE, T), T>>>(srch, dsth, starth, curh, dish, csrch, cswh, NE);

    #define CONV1(OUT, IN, BIAS) \
        k_conv_csr<<<nb((long)NN * 32, T), T>>>((float4*)(OUT), (const float4*)(IN), \
                                                start1, csrc1, csw1, inv1, (BIAS));
    #define CONVH(OUT, IN, BIAS) \
        k_conv_csr<<<nb((long)NN * 32, T), T>>>((float4*)(OUT), (const float4*)(IN), \
                                                starth, csrch, cswh, invh, (BIAS));

    // h1 = x @ W1
    k_gemm<NF, false, false><<<nb(NN, 64), 128>>>(x, W1, nullptr, A, NN);

    // encoder1: B = conv(h1); D = conv(relu(B)@W2)  (relu deferred to consumers)
    CONV1(B, A, b1);
    k_gemm<FD, false, true><<<nb(NN, 64), 128>>>(B, W2, nullptr, C, NN);
    CONV1(D, C, b2);                                    // relu(D) = embed1

    // encoder3 MLP: embed3 = relu(relu(D)@M1+mb1)@M2+mb2
    k_gemm<FD, true, true><<<nb(NN, 64), 128>>>(D, M1, mb1, B, NN);
    k_gemm<FD, true, true><<<nb(NN, 64), 128>>>(B, M2, mb2, C, NN);   // C = embed3

    // encoder2: embed2 = conv_hop(relu(D) @ W3)
    k_gemm<FD, false, true><<<nb(NN, 64), 128>>>(D, W3, nullptr, B, NN);
    CONVH(Ebuf, B, b3);                                 // Ebuf = embed2

    // u = embed3 @ Wd0 ; score = sigmoid(<u, embed2>)
    k_gemm<FD, false, false><<<nb(NN, 64), 128>>>(C, Wd, nullptr, B, NN);  // B = u (keep)
    k_rowdot<<<nb((long)NN * 32, T), T>>>(out, (const float4*)B, (const float4*)Ebuf, 10, NN);

    // permuted path: (x@W1)[perm]
    k_gather<<<nb((long)NN * 32, T), T>>>((float4*)Ebuf, (const float4*)A, perm, NN);
    CONV1(A, Ebuf, b1);
    k_gemm<FD, false, true><<<nb(NN, 64), 128>>>(A, W2, nullptr, Ebuf, NN);
    CONV1(A, Ebuf, b2);                                 // relu(A) = embed1_bad
    k_gemm<FD, false, true><<<nb(NN, 64), 128>>>(A, W3, nullptr, Ebuf, NN);
    CONVH(A, Ebuf, b3);                                 // A = embed2_bad
    k_rowdot<<<nb((long)NN * 32, T), T>>>(out, (const float4*)B, (const float4*)A, 11, NN);

    // classifier: out[:,0:10] = conv(relu(D) @ Wc) + bc
    k_gemm_wc<<<nb((long)NN * NC, T), T>>>(F, D, Wc, NN);
    k_conv_csr_nc<<<nb((long)NN * 32, T), T>>>(out, F, start1, csrc1, csw1, inv1, bc);

    #undef CONV1
    #undef CONVH
}

// round 6
// speedup vs baseline: 2.2838x; 1.5049x over previous
#include <cuda_runtime.h>
#include <cuda_bf16.h>
#include <math.h>
#include <stdint.h>

#define NN 100000
#define NE 1600000
#define NF 512
#define FD 128
#define NC 10

#define SCAN_B 512
#define SCAN_NBLK ((NN + SCAN_B - 1) / SCAN_B)

// ---------------- device scratch (static, no allocs) ----------------
__device__ __align__(16) float g_A[NN * FD];
__device__ __align__(16) float g_B[NN * FD];
__device__ __align__(16) float g_C[NN * FD];
__device__ __align__(16) float g_D[NN * FD];
__device__ __align__(16) float g_E[NN * FD];
__device__ __align__(16) float g_F[NN * NC];
__device__ int   g_cnt1[NN], g_cnth[NN];
__device__ int   g_cur1[NN], g_curh[NN];
__device__ int   g_start1[NN + 1], g_starth[NN + 1];
__device__ int   g_part[SCAN_NBLK];
__device__ float g_inv1[NN], g_dis1[NN], g_invh[NN], g_dish[NN];
__device__ int   g_csrc1[NE], g_csrch[NE];
__device__ float g_csw1[NE], g_cswh[NE];

// ---------------- degree / CSR build ----------------
__global__ void k_zero(int* a, int* b, int* c, int* d, int n) {
    int i = blockIdx.x * blockDim.x + threadIdx.x;
    if (i < n) { a[i] = 0; b[i] = 0; c[i] = 0; d[i] = 0; }
}

__global__ void k_count(const int* __restrict__ d1, const int* __restrict__ dh,
                        int* cnt1, int* cnth, int e) {
    int i = blockIdx.x * blockDim.x + threadIdx.x;
    if (i < e) {
        atomicAdd(&cnt1[d1[i]], 1);
        atomicAdd(&cnth[dh[i]], 1);
    }
}

__global__ void k_finish(const int* __restrict__ cnt1, const int* __restrict__ cnth,
                         float* inv1, float* dis1, float* invh, float* dish, int n) {
    int i = blockIdx.x * blockDim.x + threadIdx.x;
    if (i < n) {
        float d = (float)cnt1[i] + 1.0f;
        inv1[i] = 1.0f / d;
        dis1[i] = rsqrtf(d);
        float dh = (float)cnth[i] + 1.0f;
        invh[i] = 1.0f / dh;
        dish[i] = rsqrtf(dh);
    }
}

__global__ void k_scan1(const int* __restrict__ cnt, int* part, int n) {
    __shared__ int sh[SCAN_B];
    int i = blockIdx.x * SCAN_B + threadIdx.x;
    sh[threadIdx.x] = (i < n) ? cnt[i] : 0;
    __syncthreads();
    for (int off = SCAN_B / 2; off > 0; off >>= 1) {
        if (threadIdx.x < off) sh[threadIdx.x] += sh[threadIdx.x + off];
        __syncthreads();
    }
    if (threadIdx.x == 0) part[blockIdx.x] = sh[0];
}

__global__ void k_scan2(int* part, int nblk) {
    if (threadIdx.x == 0 && blockIdx.x == 0) {
        int run = 0;
        for (int b = 0; b < nblk; b++) { int v = part[b]; part[b] = run; run += v; }
    }
}

__global__ void k_scan3(const int* __restrict__ cnt, const int* __restrict__ part,
                        int* start, int n) {
    __shared__ int sh[SCAN_B];
    int i = blockIdx.x * SCAN_B + threadIdx.x;
    int v = (i < n) ? cnt[i] : 0;
    sh[threadIdx.x] = v;
    __syncthreads();
    for (int off = 1; off < SCAN_B; off <<= 1) {
        int t = (threadIdx.x >= off) ? sh[threadIdx.x - off] : 0;
        __syncthreads();
        sh[threadIdx.x] += t;
        __syncthreads();
    }
    if (i < n) {
        int excl = sh[threadIdx.x] - v + part[blockIdx.x];
        start[i] = excl;
        if (i == n - 1) start[n] = excl + v;
    }
}

__global__ void k_fill(const int* __restrict__ src, const int* __restrict__ dst,
                       const int* __restrict__ start, int* cur,
                       const float* __restrict__ dis,
                       int* csrc, float* csw, int e) {
    int i = blockIdx.x * blockDim.x + threadIdx.x;
    if (i >= e) return;
    int s = src[i], d = dst[i];
    int pos = start[d] + atomicAdd(&cur[d], 1);
    csrc[pos] = s;
    csw[pos] = dis[s] * dis[d];
}

// ---------------- CSR GCN conv: warp per node, 128 features ----------------
__global__ void __launch_bounds__(256) k_conv_csr(
    float4* __restrict__ out, const float4* __restrict__ in,
    const int* __restrict__ start, const int* __restrict__ csrc,
    const float* __restrict__ csw, const float* __restrict__ inv,
    const float* __restrict__ bias) {
    int gid = blockIdx.x * blockDim.x + threadIdx.x;
    int node = gid >> 5, lane = gid & 31;
    if (node >= NN) return;
    int e0 = start[node], e1 = start[node + 1];
    float iv = inv[node];
    float4 b = ((const float4*)bias)[lane];
    float4 v = in[(size_t)node * 32 + lane];
    float ax = fmaf(v.x, iv, b.x), ay = fmaf(v.y, iv, b.y);
    float az = fmaf(v.z, iv, b.z), aw = fmaf(v.w, iv, b.w);
    #pragma unroll 4
    for (int e = e0; e < e1; e++) {
        int s = __ldg(&csrc[e]);
        float w = __ldg(&csw[e]);
        float4 u = __ldg(in + (size_t)s * 32 + lane);
        ax = fmaf(u.x, w, ax); ay = fmaf(u.y, w, ay);
        az = fmaf(u.z, w, az); aw = fmaf(u.w, w, aw);
    }
    out[(size_t)node * 32 + lane] = make_float4(ax, ay, az, aw);
}

// classifier conv: warp per node, 10 features, writes out[:,0:10]
__global__ void __launch_bounds__(256) k_conv_csr_nc(
    float* __restrict__ out, const float* __restrict__ F,
    const int* __restrict__ start, const int* __restrict__ csrc,
    const float* __restrict__ csw, const float* __restrict__ inv,
    const float* __restrict__ bc) {
    int gid = blockIdx.x * blockDim.x + threadIdx.x;
    int node = gid >> 5, lane = gid & 31;
    if (node >= NN) return;
    int e0 = start[node], e1 = start[node + 1];
    float acc = 0.0f;
    if (lane < NC)
        acc = fmaf(F[(size_t)node * NC + lane], inv[node], bc[lane]);
    #pragma unroll 4
    for (int e = e0; e < e1; e++) {
        int s = __ldg(&csrc[e]);
        float w = __ldg(&csw[e]);
        if (lane < NC) acc = fmaf(__ldg(&F[(size_t)s * NC + lane]), w, acc);
    }
    if (lane < NC) out[(size_t)node * 12 + lane] = acc;
}

__global__ void k_gather(float4* __restrict__ out, const float4* __restrict__ in,
                         const int* __restrict__ perm, int n) {
    int idx = blockIdx.x * blockDim.x + threadIdx.x;
    if (idx >= n * 32) return;
    int i = idx >> 5, q = idx & 31;
    out[idx] = in[(size_t)perm[i] * 32 + q];
}

// ---------------- tensor-core GEMM (bf16 3-MMA split, fp32-quality) ----------------
// C[n,128] = act(A)[n,K] @ W[K,128] (+bias)
__device__ __forceinline__ uint32_t pack_bf2(__nv_bfloat16 a, __nv_bfloat16 b) {
    __nv_bfloat162 t = __nv_bfloat162(a, b);
    return *reinterpret_cast<uint32_t*>(&t);
}

__device__ __forceinline__ void split2(float x, float y, uint32_t& hi, uint32_t& lo) {
    __nv_bfloat16 h0 = __float2bfloat16_rn(x);
    __nv_bfloat16 h1 = __float2bfloat16_rn(y);
    float r0 = x - __bfloat162float(h0);
    float r1 = y - __bfloat162float(h1);
    hi = pack_bf2(h0, h1);
    lo = pack_bf2(__float2bfloat16_rn(r0), __float2bfloat16_rn(r1));
}

__device__ __forceinline__ void mma_bf16(float* c, uint32_t a0, uint32_t a1,
                                         uint32_t a2, uint32_t a3,
                                         uint32_t b0, uint32_t b1) {
    asm volatile(
        "mma.sync.aligned.m16n8k16.row.col.f32.bf16.bf16.f32 "
        "{%0,%1,%2,%3}, {%4,%5,%6,%7}, {%8,%9}, {%0,%1,%2,%3};"
        : "+f"(c[0]), "+f"(c[1]), "+f"(c[2]), "+f"(c[3])
        : "r"(a0), "r"(a1), "r"(a2), "r"(a3), "r"(b0), "r"(b1));
}

#define SMS 136   // smem row stride (words): fragment-read bank = 8*(l%4)+(l/4), conflict-free

template <int K, bool BIAS, bool RELUIN>
__global__ void __launch_bounds__(256) k_gemm_tc(const float* __restrict__ A,
                                                 const float* __restrict__ W,
                                                 const float* __restrict__ bias,
                                                 float* __restrict__ C, int n) {
    __shared__ uint32_t sAh[8][SMS], sAl[8][SMS], sBh[8][SMS], sBl[8][SMS];
    const int tid = threadIdx.x;
    const int lane = tid & 31;
    const int wrp = tid >> 5;
    const int mw = (wrp & 3) * 32;     // warp m-base within tile
    const int nwb = (wrp >> 2) * 64;   // warp n-base within tile
    const int r = lane >> 2;           // 0..7
    const int q = lane & 3;            // 0..3
    const int m0 = blockIdx.x * 128;

    float acc[2][8][4];
    #pragma unroll
    for (int mi = 0; mi < 2; mi++)
        #pragma unroll
        for (int ni = 0; ni < 8; ni++)
            #pragma unroll
            for (int j = 0; j < 4; j++) acc[mi][ni][j] = 0.0f;

    // loader indices
    const int lm = tid >> 1;          // 0..127 (A row within tile)
    const int lhalf = tid & 1;        // 0..1
    const int lnn = tid & 127;        // W col
    const int lp = tid >> 7;          // 0..1

    for (int k0 = 0; k0 < K; k0 += 16) {
        // ---- load A tile [128 x 16] ----
        {
            bool valid = (m0 + lm) < n;
            const float* arow = A + (size_t)(m0 + lm) * K + k0 + lhalf * 8;
            #pragma unroll
            for (int j = 0; j < 2; j++) {
                float4 v = make_float4(0.f, 0.f, 0.f, 0.f);
                if (valid) v = *(const float4*)(arow + j * 4);
                if (RELUIN) {
                    v.x = fmaxf(v.x, 0.f); v.y = fmaxf(v.y, 0.f);
                    v.z = fmaxf(v.z, 0.f); v.w = fmaxf(v.w, 0.f);
                }
                int kq = lhalf * 4 + j * 2;
                uint32_t hi, lo;
                split2(v.x, v.y, hi, lo);
                sAh[kq][lm] = hi; sAl[kq][lm] = lo;
                split2(v.z, v.w, hi, lo);
                sAh[kq + 1][lm] = hi; sAl[kq + 1][lm] = lo;
            }
        }
        // ---- load W tile [16 x 128], packed (k,k+1) pairs per column ----
        {
            #pragma unroll
            for (int qq = 0; qq < 4; qq++) {
                int kq = lp * 4 + qq;
                float w0 = __ldg(&W[(size_t)(k0 + 2 * kq) * 128 + lnn]);
                float w1 = __ldg(&W[(size_t)(k0 + 2 * kq + 1) * 128 + lnn]);
                uint32_t hi, lo;
                split2(w0, w1, hi, lo);
                sBh[kq][lnn] = hi; sBl[kq][lnn] = lo;
            }
        }
        __syncthreads();

        // ---- fragments + mma ----
        uint32_t bh[8][2], bl[8][2];
        #pragma unroll
        for (int ni = 0; ni < 8; ni++) {
            int nc = nwb + ni * 8 + r;
            bh[ni][0] = sBh[q][nc];     bh[ni][1] = sBh[q + 4][nc];
            bl[ni][0] = sBl[q][nc];     bl[ni][1] = sBl[q + 4][nc];
        }
        #pragma unroll
        for (int mi = 0; mi < 2; mi++) {
            int mb = mw + mi * 16;
            uint32_t ah0 = sAh[q][mb + r],     ah1 = sAh[q][mb + r + 8];
            uint32_t ah2 = sAh[q + 4][mb + r], ah3 = sAh[q + 4][mb + r + 8];
            uint32_t al0 = sAl[q][mb + r],     al1 = sAl[q][mb + r + 8];
            uint32_t al2 = sAl[q + 4][mb + r], al3 = sAl[q + 4][mb + r + 8];
            #pragma unroll
            for (int ni = 0; ni < 8; ni++) {
                mma_bf16(acc[mi][ni], ah0, ah1, ah2, ah3, bh[ni][0], bh[ni][1]);
                mma_bf16(acc[mi][ni], ah0, ah1, ah2, ah3, bl[ni][0], bl[ni][1]);
                mma_bf16(acc[mi][ni], al0, al1, al2, al3, bh[ni][0], bh[ni][1]);
            }
        }
        __syncthreads();
    }

    // ---- epilogue ----
    #pragma unroll
    for (int mi = 0; mi < 2; mi++) {
        #pragma unroll
        for (int ni = 0; ni < 8; ni++) {
            int row = m0 + mw + mi * 16 + r;
            int col = nwb + ni * 8 + q * 2;
            float b0 = BIAS ? bias[col] : 0.0f;
            float b1 = BIAS ? bias[col + 1] : 0.0f;
            if (row < n)
                *(float2*)&C[(size_t)row * 128 + col] =
                    make_float2(acc[mi][ni][0] + b0, acc[mi][ni][1] + b1);
            if (row + 8 < n)
                *(float2*)&C[(size_t)(row + 8) * 128 + col] =
                    make_float2(acc[mi][ni][2] + b0, acc[mi][ni][3] + b1);
        }
    }
}

// ---------------- bilinear score ----------------
__global__ void k_rowdot(float* __restrict__ out, const float4* __restrict__ u,
                         const float4* __restrict__ v, int col, int n) {
    int gid = blockIdx.x * blockDim.x + threadIdx.x;
    int i = gid >> 5, lane = gid & 31;
    if (i >= n) return;
    float4 a = u[(size_t)i * 32 + lane];
    float4 b = v[(size_t)i * 32 + lane];
    float s = a.x * b.x + a.y * b.y + a.z * b.z + a.w * b.w;
    #pragma unroll
    for (int off = 16; off > 0; off >>= 1)
        s += __shfl_down_sync(0xffffffffu, s, off);
    if (lane == 0) out[(size_t)i * 12 + col] = 1.0f / (1.0f + expf(-s));
}

// ---------------- classifier pre-GEMM: F[n,10] = relu(D) @ Wc ----------------
__global__ void k_gemm_wc(float* __restrict__ F, const float* __restrict__ D,
                          const float* __restrict__ Wc, int n) {
    __shared__ float wcs[FD * NC];
    for (int t = threadIdx.x; t < FD * NC; t += blockDim.x) wcs[t] = Wc[t];
    __syncthreads();
    int gid = blockIdx.x * blockDim.x + threadIdx.x;
    if (gid >= n * NC) return;
    int i = gid / NC, j = gid % NC;
    const float* drow = &D[(size_t)i * FD];
    float s = 0.0f;
    #pragma unroll
    for (int k = 0; k < FD; k++)
        s = fmaf(fmaxf(__ldg(&drow[k]), 0.0f), wcs[k * NC + j], s);
    F[gid] = s;
}

// ---------------- launch ----------------
static inline int nb(long total, int tpb) { return (int)((total + tpb - 1) / tpb); }

extern "C" void kernel_launch(void* const* d_in, const int* in_sizes, int n_in,
                              void* d_out, int out_size) {
    const float* x    = (const float*)d_in[0];
    const int*   e1   = (const int*)d_in[1];
    const int*   eh   = (const int*)d_in[2];
    const int*   perm = (const int*)d_in[4];
    const float* W1 = (const float*)d_in[5];
    const float* b1 = (const float*)d_in[6];
    const float* W2 = (const float*)d_in[7];
    const float* b2 = (const float*)d_in[8];
    const float* W3 = (const float*)d_in[9];
    const float* b3 = (const float*)d_in[10];
    const float* M1 = (const float*)d_in[11];
    const float* mb1 = (const float*)d_in[12];
    const float* M2 = (const float*)d_in[13];
    const float* mb2 = (const float*)d_in[14];
    const float* Wc = (const float*)d_in[15];
    const float* bc = (const float*)d_in[16];
    const float* Wd = (const float*)d_in[17];
    float* out = (float*)d_out;

    const int* src1 = e1;       const int* dst1 = e1 + NE;
    const int* srch = eh;       const int* dsth = eh + NE;

    float *A, *B, *C, *D, *Ebuf, *F;
    float *inv1, *dis1, *invh, *dish, *csw1, *cswh;
    int *cnt1, *cnth, *cur1, *curh, *start1, *starth, *part, *csrc1, *csrch;
    cudaGetSymbolAddress((void**)&A, g_A);
    cudaGetSymbolAddress((void**)&B, g_B);
    cudaGetSymbolAddress((void**)&C, g_C);
    cudaGetSymbolAddress((void**)&D, g_D);
    cudaGetSymbolAddress((void**)&Ebuf, g_E);
    cudaGetSymbolAddress((void**)&F, g_F);
    cudaGetSymbolAddress((void**)&cnt1, g_cnt1);
    cudaGetSymbolAddress((void**)&cnth, g_cnth);
    cudaGetSymbolAddress((void**)&cur1, g_cur1);
    cudaGetSymbolAddress((void**)&curh, g_curh);
    cudaGetSymbolAddress((void**)&start1, g_start1);
    cudaGetSymbolAddress((void**)&starth, g_starth);
    cudaGetSymbolAddress((void**)&part, g_part);
    cudaGetSymbolAddress((void**)&inv1, g_inv1);
    cudaGetSymbolAddress((void**)&dis1, g_dis1);
    cudaGetSymbolAddress((void**)&invh, g_invh);
    cudaGetSymbolAddress((void**)&dish, g_dish);
    cudaGetSymbolAddress((void**)&csrc1, g_csrc1);
    cudaGetSymbolAddress((void**)&csrch, g_csrch);
    cudaGetSymbolAddress((void**)&csw1, g_csw1);
    cudaGetSymbolAddress((void**)&cswh, g_cswh);

    const int T = 256;
    const int GB = nb(NN, 128);   // gemm blocks

    // ---- CSR build (both graphs) ----
    k_zero<<<nb(NN, T), T>>>(cnt1, cnth, cur1, curh, NN);
    k_count<<<nb(NE, T), T>>>(dst1, dsth, cnt1, cnth, NE);
    k_finish<<<nb(NN, T), T>>>(cnt1, cnth, inv1, dis1, invh, dish, NN);
    k_scan1<<<SCAN_NBLK, SCAN_B>>>(cnt1, part, NN);
    k_scan2<<<1, 32>>>(part, SCAN_NBLK);
    k_scan3<<<SCAN_NBLK, SCAN_B>>>(cnt1, part, start1, NN);
    k_scan1<<<SCAN_NBLK, SCAN_B>>>(cnth, part, NN);
    k_scan2<<<1, 32>>>(part, SCAN_NBLK);
    k_scan3<<<SCAN_NBLK, SCAN_B>>>(cnth, part, starth, NN);
    k_fill<<<nb(NE, T), T>>>(src1, dst1, start1, cur1, dis1, csrc1, csw1, NE);
    k_fill<<<nb(NE, T), T>>>(srch, dsth, starth, curh, dish, csrch, cswh, NE);

    #define CONV1(OUT, IN, BIAS) \
        k_conv_csr<<<nb((long)NN * 32, T), T>>>((float4*)(OUT), (const float4*)(IN), \
                                                start1, csrc1, csw1, inv1, (BIAS));
    #define CONVH(OUT, IN, BIAS) \
        k_conv_csr<<<nb((long)NN * 32, T), T>>>((float4*)(OUT), (const float4*)(IN), \
                                                starth, csrch, cswh, invh, (BIAS));

    // h1 = x @ W1
    k_gemm_tc<NF, false, false><<<GB, 256>>>(x, W1, nullptr, A, NN);

    // encoder1: B = conv(h1); D = conv(relu(B)@W2)  (relu deferred to consumers)
    CONV1(B, A, b1);
    k_gemm_tc<FD, false, true><<<GB, 256>>>(B, W2, nullptr, C, NN);
    CONV1(D, C, b2);                                    // relu(D) = embed1

    // encoder3 MLP: embed3 = relu(relu(D)@M1+mb1)@M2+mb2
    k_gemm_tc<FD, true, true><<<GB, 256>>>(D, M1, mb1, B, NN);
    k_gemm_tc<FD, true, true><<<GB, 256>>>(B, M2, mb2, C, NN);   // C = embed3

    // encoder2: embed2 = conv_hop(relu(D) @ W3)
    k_gemm_tc<FD, false, true><<<GB, 256>>>(D, W3, nullptr, B, NN);
    CONVH(Ebuf, B, b3);                                 // Ebuf = embed2

    // u = embed3 @ Wd0 ; score = sigmoid(<u, embed2>)
    k_gemm_tc<FD, false, false><<<GB, 256>>>(C, Wd, nullptr, B, NN);  // B = u (keep)
    k_rowdot<<<nb((long)NN * 32, T), T>>>(out, (const float4*)B, (const float4*)Ebuf, 10, NN);

    // permuted path: (x@W1)[perm]
    k_gather<<<nb((long)NN * 32, T), T>>>((float4*)Ebuf, (const float4*)A, perm, NN);
    CONV1(A, Ebuf, b1);
    k_gemm_tc<FD, false, true><<<GB, 256>>>(A, W2, nullptr, Ebuf, NN);
    CONV1(A, Ebuf, b2);                                 // relu(A) = embed1_bad
    k_gemm_tc<FD, false, true><<<GB, 256>>>(A, W3, nullptr, Ebuf, NN);
    CONVH(A, Ebuf, b3);                                 // A = embed2_bad
    k_rowdot<<<nb((long)NN * 32, T), T>>>(out, (const float4*)B, (const float4*)A, 11, NN);

    // classifier: out[:,0:10] = conv(relu(D) @ Wc) + bc
    k_gemm_wc<<<nb((long)NN * NC, T), T>>>(F, D, Wc, NN);
    k_conv_csr_nc<<<nb((long)NN * 32, T), T>>>(out, F, start1, csrc1, csw1, inv1, bc);

    #undef CONV1
    #undef CONVH
}

// round 8
// speedup vs baseline: 2.4147x; 1.0573x over previous
#include <cuda_runtime.h>
#include <cuda_bf16.h>
#include <math.h>
#include <stdint.h>

#define NN 100000
#define NE 1600000
#define NF 512
#define FD 128
#define NC 10

#define SCAN_B 512
#define SCAN_NBLK ((NN + SCAN_B - 1) / SCAN_B)

// ---------------- device scratch (static, no allocs) ----------------
__device__ __align__(16) float g_A[NN * FD];
__device__ __align__(16) float g_B[NN * FD];
__device__ __align__(16) float g_C[NN * FD];
__device__ __align__(16) float g_D[NN * FD];
__device__ __align__(16) float g_E[NN * FD];
__device__ __align__(16) float g_F[NN * NC];
__device__ int   g_cnt1[NN], g_cnth[NN];
__device__ int   g_cur1[NN], g_curh[NN];
__device__ int   g_start1[NN + 1], g_starth[NN + 1];
__device__ int   g_part[SCAN_NBLK];
__device__ float g_inv1[NN], g_dis1[NN], g_invh[NN], g_dish[NN];
__device__ __align__(8) int2 g_edge1[NE], g_edgeh[NE];   // (src, weight-bits)

// ---------------- degree / CSR build ----------------
__global__ void k_zero(int* a, int* b, int* c, int* d, int n) {
    int i = blockIdx.x * blockDim.x + threadIdx.x;
    if (i < n) { a[i] = 0; b[i] = 0; c[i] = 0; d[i] = 0; }
}

__global__ void k_count(const int* __restrict__ d1, const int* __restrict__ dh,
                        int* cnt1, int* cnth, int e) {
    int i = blockIdx.x * blockDim.x + threadIdx.x;
    if (i < e) {
        atomicAdd(&cnt1[d1[i]], 1);
        atomicAdd(&cnth[dh[i]], 1);
    }
}

__global__ void k_finish(const int* __restrict__ cnt1, const int* __restrict__ cnth,
                         float* inv1, float* dis1, float* invh, float* dish, int n) {
    int i = blockIdx.x * blockDim.x + threadIdx.x;
    if (i < n) {
        float d = (float)cnt1[i] + 1.0f;
        inv1[i] = 1.0f / d;
        dis1[i] = rsqrtf(d);
        float dh = (float)cnth[i] + 1.0f;
        invh[i] = 1.0f / dh;
        dish[i] = rsqrtf(dh);
    }
}

__global__ void k_scan1(const int* __restrict__ cnt, int* part, int n) {
    __shared__ int sh[SCAN_B];
    int i = blockIdx.x * SCAN_B + threadIdx.x;
    sh[threadIdx.x] = (i < n) ? cnt[i] : 0;
    __syncthreads();
    for (int off = SCAN_B / 2; off > 0; off >>= 1) {
        if (threadIdx.x < off) sh[threadIdx.x] += sh[threadIdx.x + off];
        __syncthreads();
    }
    if (threadIdx.x == 0) part[blockIdx.x] = sh[0];
}

__global__ void k_scan2(int* part, int nblk) {
    if (threadIdx.x == 0 && blockIdx.x == 0) {
        int run = 0;
        for (int b = 0; b < nblk; b++) { int v = part[b]; part[b] = run; run += v; }
    }
}

__global__ void k_scan3(const int* __restrict__ cnt, const int* __restrict__ part,
                        int* start, int n) {
    __shared__ int sh[SCAN_B];
    int i = blockIdx.x * SCAN_B + threadIdx.x;
    int v = (i < n) ? cnt[i] : 0;
    sh[threadIdx.x] = v;
    __syncthreads();
    for (int off = 1; off < SCAN_B; off <<= 1) {
        int t = (threadIdx.x >= off) ? sh[threadIdx.x - off] : 0;
        __syncthreads();
        sh[threadIdx.x] += t;
        __syncthreads();
    }
    if (i < n) {
        int excl = sh[threadIdx.x] - v + part[blockIdx.x];
        start[i] = excl;
        if (i == n - 1) start[n] = excl + v;
    }
}

__global__ void k_fill(const int* __restrict__ src, const int* __restrict__ dst,
                       const int* __restrict__ start, int* cur,
                       const float* __restrict__ dis,
                       int2* __restrict__ edges, int e) {
    int i = blockIdx.x * blockDim.x + threadIdx.x;
    if (i >= e) return;
    int s = src[i], d = dst[i];
    int pos = start[d] + atomicAdd(&cur[d], 1);
    edges[pos] = make_int2(s, __float_as_int(dis[s] * dis[d]));
}

// ---------------- CSR GCN conv: warp per node, 128 features ----------------
__global__ void __launch_bounds__(256) k_conv_csr(
    float4* __restrict__ out, const float4* __restrict__ in,
    const int* __restrict__ start, const int2* __restrict__ edges,
    const float* __restrict__ inv, const float* __restrict__ bias) {
    int gid = blockIdx.x * blockDim.x + threadIdx.x;
    int node = gid >> 5, lane = gid & 31;
    if (node >= NN) return;
    int e0 = start[node], e1 = start[node + 1];
    float iv = inv[node];
    float4 b = ((const float4*)bias)[lane];
    float4 v = in[(size_t)node * 32 + lane];
    float ax = fmaf(v.x, iv, b.x), ay = fmaf(v.y, iv, b.y);
    float az = fmaf(v.z, iv, b.z), aw = fmaf(v.w, iv, b.w);
    #pragma unroll 4
    for (int e = e0; e < e1; e++) {
        int2 ed = __ldg(&edges[e]);
        float w = __int_as_float(ed.y);
        float4 u = __ldg(in + (size_t)ed.x * 32 + lane);
        ax = fmaf(u.x, w, ax); ay = fmaf(u.y, w, ay);
        az = fmaf(u.z, w, az); aw = fmaf(u.w, w, aw);
    }
    out[(size_t)node * 32 + lane] = make_float4(ax, ay, az, aw);
}

// classifier conv: warp per node, 10 features, writes out[:,0:10]
__global__ void __launch_bounds__(256) k_conv_csr_nc(
    float* __restrict__ out, const float* __restrict__ F,
    const int* __restrict__ start, const int2* __restrict__ edges,
    const float* __restrict__ inv, const float* __restrict__ bc) {
    int gid = blockIdx.x * blockDim.x + threadIdx.x;
    int node = gid >> 5, lane = gid & 31;
    if (node >= NN) return;
    int e0 = start[node], e1 = start[node + 1];
    float acc = 0.0f;
    if (lane < NC)
        acc = fmaf(F[(size_t)node * NC + lane], inv[node], bc[lane]);
    #pragma unroll 4
    for (int e = e0; e < e1; e++) {
        int2 ed = __ldg(&edges[e]);
        float w = __int_as_float(ed.y);
        if (lane < NC) acc = fmaf(__ldg(&F[(size_t)ed.x * NC + lane]), w, acc);
    }
    if (lane < NC) out[(size_t)node * 12 + lane] = acc;
}

__global__ void k_gather(float4* __restrict__ out, const float4* __restrict__ in,
                         const int* __restrict__ perm, int n) {
    int idx = blockIdx.x * blockDim.x + threadIdx.x;
    if (idx >= n * 32) return;
    int i = idx >> 5, q = idx & 31;
    out[idx] = in[(size_t)perm[i] * 32 + q];
}

// ---------------- tensor-core GEMM (bf16 3-MMA split, 2-stage pipeline) ----------------
__device__ __forceinline__ uint32_t pack_bf2(__nv_bfloat16 a, __nv_bfloat16 b) {
    __nv_bfloat162 t = __nv_bfloat162(a, b);
    return *reinterpret_cast<uint32_t*>(&t);
}

__device__ __forceinline__ void split2(float x, float y, uint32_t& hi, uint32_t& lo) {
    __nv_bfloat16 h0 = __float2bfloat16_rn(x);
    __nv_bfloat16 h1 = __float2bfloat16_rn(y);
    float r0 = x - __bfloat162float(h0);
    float r1 = y - __bfloat162float(h1);
    hi = pack_bf2(h0, h1);
    lo = pack_bf2(__float2bfloat16_rn(r0), __float2bfloat16_rn(r1));
}

__device__ __forceinline__ void mma_bf16(float* c, uint32_t a0, uint32_t a1,
                                         uint32_t a2, uint32_t a3,
                                         uint32_t b0, uint32_t b1) {
    asm volatile(
        "mma.sync.aligned.m16n8k16.row.col.f32.bf16.bf16.f32 "
        "{%0,%1,%2,%3}, {%4,%5,%6,%7}, {%8,%9}, {%0,%1,%2,%3};"
        : "+f"(c[0]), "+f"(c[1]), "+f"(c[2]), "+f"(c[3])
        : "r"(a0), "r"(a1), "r"(a2), "r"(a3), "r"(b0), "r"(b1));
}

#define SMS 136   // smem row stride (words), conflict-free for fragment reads

template <int K, bool BIAS, bool RELUIN>
__global__ void __launch_bounds__(256) k_gemm_tc(const float* __restrict__ A,
                                                 const float* __restrict__ W,
                                                 const float* __restrict__ bias,
                                                 float* __restrict__ C, int n) {
    __shared__ uint32_t sAh[2][8][SMS], sAl[2][8][SMS], sBh[2][8][SMS], sBl[2][8][SMS];
    const int tid = threadIdx.x;
    const int lane = tid & 31;
    const int wrp = tid >> 5;
    const int mw = (wrp & 3) * 32;
    const int nwb = (wrp >> 2) * 64;
    const int r = lane >> 2;
    const int q = lane & 3;
    const int m0 = blockIdx.x * 128;

    float acc[2][8][4];
    #pragma unroll
    for (int mi = 0; mi < 2; mi++)
        #pragma unroll
        for (int ni = 0; ni < 8; ni++)
            #pragma unroll
            for (int j = 0; j < 4; j++) acc[mi][ni][j] = 0.0f;

    const int lm = tid >> 1;
    const int lhalf = tid & 1;
    const int lnn = tid & 127;
    const int lp = tid >> 7;
    const bool valid = (m0 + lm) < n;

    float4 pa[2];
    float pw0[4], pw1[4];

    auto fetch = [&](int k0) {
        const float* arow = A + (size_t)(m0 + lm) * K + k0 + lhalf * 8;
        #pragma unroll
        for (int j = 0; j < 2; j++) {
            float4 v = make_float4(0.f, 0.f, 0.f, 0.f);
            if (valid) v = *(const float4*)(arow + j * 4);
            pa[j] = v;
        }
        #pragma unroll
        for (int qq = 0; qq < 4; qq++) {
            int kq = lp * 4 + qq;
            pw0[qq] = __ldg(&W[(size_t)(k0 + 2 * kq) * 128 + lnn]);
            pw1[qq] = __ldg(&W[(size_t)(k0 + 2 * kq + 1) * 128 + lnn]);
        }
    };

    auto stash = [&](int st) {
        #pragma unroll
        for (int j = 0; j < 2; j++) {
            float4 v = pa[j];
            if (RELUIN) {
                v.x = fmaxf(v.x, 0.f); v.y = fmaxf(v.y, 0.f);
                v.z = fmaxf(v.z, 0.f); v.w = fmaxf(v.w, 0.f);
            }
            int kq = lhalf * 4 + j * 2;
            uint32_t hi, lo;
            split2(v.x, v.y, hi, lo);
            sAh[st][kq][lm] = hi; sAl[st][kq][lm] = lo;
            split2(v.z, v.w, hi, lo);
            sAh[st][kq + 1][lm] = hi; sAl[st][kq + 1][lm] = lo;
        }
        #pragma unroll
        for (int qq = 0; qq < 4; qq++) {
            int kq = lp * 4 + qq;
            uint32_t hi, lo;
            split2(pw0[qq], pw1[qq], hi, lo);
            sBh[st][kq][lnn] = hi; sBl[st][kq][lnn] = lo;
        }
    };

    auto domma = [&](int st) {
        uint32_t bh[8][2], bl[8][2];
        #pragma unroll
        for (int ni = 0; ni < 8; ni++) {
            int nc = nwb + ni * 8 + r;
            bh[ni][0] = sBh[st][q][nc];     bh[ni][1] = sBh[st][q + 4][nc];
            bl[ni][0] = sBl[st][q][nc];     bl[ni][1] = sBl[st][q + 4][nc];
        }
        #pragma unroll
        for (int mi = 0; mi < 2; mi++) {
            int mb = mw + mi * 16;
            uint32_t ah0 = sAh[st][q][mb + r],     ah1 = sAh[st][q][mb + r + 8];
            uint32_t ah2 = sAh[st][q + 4][mb + r], ah3 = sAh[st][q + 4][mb + r + 8];
            uint32_t al0 = sAl[st][q][mb + r],     al1 = sAl[st][q][mb + r + 8];
            uint32_t al2 = sAl[st][q + 4][mb + r], al3 = sAl[st][q + 4][mb + r + 8];
            #pragma unroll
            for (int ni = 0; ni < 8; ni++) {
                mma_bf16(acc[mi][ni], ah0, ah1, ah2, ah3, bh[ni][0], bh[ni][1]);
                mma_bf16(acc[mi][ni], ah0, ah1, ah2, ah3, bl[ni][0], bl[ni][1]);
                mma_bf16(acc[mi][ni], al0, al1, al2, al3, bh[ni][0], bh[ni][1]);
            }
        }
    };

    fetch(0);
    stash(0);
    __syncthreads();
    int stage = 0;
    for (int k0 = 16; k0 < K; k0 += 16) {
        fetch(k0);          // global loads for next tile (in flight during mma)
        domma(stage);       // compute current tile
        stash(stage ^ 1);   // convert + store next tile
        __syncthreads();
        stage ^= 1;
    }
    domma(stage);

    // ---- epilogue ----
    #pragma unroll
    for (int mi = 0; mi < 2; mi++) {
        #pragma unroll
        for (int ni = 0; ni < 8; ni++) {
            int row = m0 + mw + mi * 16 + r;
            int col = nwb + ni * 8 + q * 2;
            float b0 = BIAS ? bias[col] : 0.0f;
            float b1 = BIAS ? bias[col + 1] : 0.0f;
            if (row < n)
                *(float2*)&C[(size_t)row * 128 + col] =
                    make_float2(acc[mi][ni][0] + b0, acc[mi][ni][1] + b1);
            if (row + 8 < n)
                *(float2*)&C[(size_t)(row + 8) * 128 + col] =
                    make_float2(acc[mi][ni][2] + b0, acc[mi][ni][3] + b1);
        }
    }
}

// ---------------- bilinear score ----------------
__global__ void k_rowdot(float* __restrict__ out, const float4* __restrict__ u,
                         const float4* __restrict__ v, int col, int n) {
    int gid = blockIdx.x * blockDim.x + threadIdx.x;
    int i = gid >> 5, lane = gid & 31;
    if (i >= n) return;
    float4 a = u[(size_t)i * 32 + lane];
    float4 b = v[(size_t)i * 32 + lane];
    float s = a.x * b.x + a.y * b.y + a.z * b.z + a.w * b.w;
    #pragma unroll
    for (int off = 16; off > 0; off >>= 1)
        s += __shfl_down_sync(0xffffffffu, s, off);
    if (lane == 0) out[(size_t)i * 12 + col] = 1.0f / (1.0f + expf(-s));
}

// ---------------- classifier pre-GEMM: F[n,10] = relu(D) @ Wc ----------------
__global__ void k_gemm_wc(float* __restrict__ F, const float* __restrict__ D,
                          const float* __restrict__ Wc, int n) {
    __shared__ float wcs[FD * NC];
    for (int t = threadIdx.x; t < FD * NC; t += blockDim.x) wcs[t] = Wc[t];
    __syncthreads();
    int gid = blockIdx.x * blockDim.x + threadIdx.x;
    if (gid >= n * NC) return;
    int i = gid / NC, j = gid % NC;
    const float* drow = &D[(size_t)i * FD];
    float s = 0.0f;
    #pragma unroll
    for (int k = 0; k < FD; k++)
        s = fmaf(fmaxf(__ldg(&drow[k]), 0.0f), wcs[k * NC + j], s);
    F[gid] = s;
}

// ---------------- launch ----------------
static inline int nb(long total, int tpb) { return (int)((total + tpb - 1) / tpb); }

extern "C" void kernel_launch(void* const* d_in, const int* in_sizes, int n_in,
                              void* d_out, int out_size) {
    const float* x    = (const float*)d_in[0];
    const int*   e1   = (const int*)d_in[1];
    const int*   eh   = (const int*)d_in[2];
    const int*   perm = (const int*)d_in[4];
    const float* W1 = (const float*)d_in[5];
    const float* b1 = (const float*)d_in[6];
    const float* W2 = (const float*)d_in[7];
    const float* b2 = (const float*)d_in[8];
    const float* W3 = (const float*)d_in[9];
    const float* b3 = (const float*)d_in[10];
    const float* M1 = (const float*)d_in[11];
    const float* mb1 = (const float*)d_in[12];
    const float* M2 = (const float*)d_in[13];
    const float* mb2 = (const float*)d_in[14];
    const float* Wc = (const float*)d_in[15];
    const float* bc = (const float*)d_in[16];
    const float* Wd = (const float*)d_in[17];
    float* out = (float*)d_out;

    const int* src1 = e1;       const int* dst1 = e1 + NE;
    const int* srch = eh;       const int* dsth = eh + NE;

    float *A, *B, *C, *D, *Ebuf, *F;
    float *inv1, *dis1, *invh, *dish;
    int *cnt1, *cnth, *cur1, *curh, *start1, *starth, *part;
    int2 *edge1, *edgeh;
    cudaGetSymbolAddress((void**)&A, g_A);
    cudaGetSymbolAddress((void**)&B, g_B);
    cudaGetSymbolAddress((void**)&C, g_C);
    cudaGetSymbolAddress((void**)&D, g_D);
    cudaGetSymbolAddress((void**)&Ebuf, g_E);
    cudaGetSymbolAddress((void**)&F, g_F);
    cudaGetSymbolAddress((void**)&cnt1, g_cnt1);
    cudaGetSymbolAddress((void**)&cnth, g_cnth);
    cudaGetSymbolAddress((void**)&cur1, g_cur1);
    cudaGetSymbolAddress((void**)&curh, g_curh);
    cudaGetSymbolAddress((void**)&start1, g_start1);
    cudaGetSymbolAddress((void**)&starth, g_starth);
    cudaGetSymbolAddress((void**)&part, g_part);
    cudaGetSymbolAddress((void**)&inv1, g_inv1);
    cudaGetSymbolAddress((void**)&dis1, g_dis1);
    cudaGetSymbolAddress((void**)&invh, g_invh);
    cudaGetSymbolAddress((void**)&dish, g_dish);
    cudaGetSymbolAddress((void**)&edge1, g_edge1);
    cudaGetSymbolAddress((void**)&edgeh, g_edgeh);

    const int T = 256;
    const int GB = nb(NN, 128);

    // ---- CSR build (both graphs) ----
    k_zero<<<nb(NN, T), T>>>(cnt1, cnth, cur1, curh, NN);
    k_count<<<nb(NE, T), T>>>(dst1, dsth, cnt1, cnth, NE);
    k_finish<<<nb(NN, T), T>>>(cnt1, cnth, inv1, dis1, invh, dish, NN);
    k_scan1<<<SCAN_NBLK, SCAN_B>>>(cnt1, part, NN);
    k_scan2<<<1, 32>>>(part, SCAN_NBLK);
    k_scan3<<<SCAN_NBLK, SCAN_B>>>(cnt1, part, start1, NN);
    // h1 = x @ W1 (independent of CSR; also shifts profiling sample)
    k_gemm_tc<NF, false, false><<<GB, 256>>>(x, W1, nullptr, A, NN);
    k_scan1<<<SCAN_NBLK, SCAN_B>>>(cnth, part, NN);
    k_scan2<<<1, 32>>>(part, SCAN_NBLK);
    k_scan3<<<SCAN_NBLK, SCAN_B>>>(cnth, part, starth, NN);
    k_fill<<<nb(NE, T), T>>>(src1, dst1, start1, cur1, dis1, edge1, NE);
    k_fill<<<nb(NE, T), T>>>(srch, dsth, starth, curh, dish, edgeh, NE);

    #define CONV1(OUT, IN, BIAS) \
        k_conv_csr<<<nb((long)NN * 32, T), T>>>((float4*)(OUT), (const float4*)(IN), \
                                                start1, edge1, inv1, (BIAS));
    #define CONVH(OUT, IN, BIAS) \
        k_conv_csr<<<nb((long)NN * 32, T), T>>>((float4*)(OUT), (const float4*)(IN), \
                                                starth, edgeh, invh, (BIAS));

    // encoder1: B = conv(h1); D = conv(relu(B)@W2)  (relu deferred to consumers)
    CONV1(B, A, b1);
    k_gemm_tc<FD, false, true><<<GB, 256>>>(B, W2, nullptr, C, NN);
    CONV1(D, C, b2);                                    // relu(D) = embed1

    // encoder3 MLP: embed3 = relu(relu(D)@M1+mb1)@M2+mb2
    k_gemm_tc<FD, true, true><<<GB, 256>>>(D, M1, mb1, B, NN);
    k_gemm_tc<FD, true, true><<<GB, 256>>>(B, M2, mb2, C, NN);   // C = embed3

    // encoder2: embed2 = conv_hop(relu(D) @ W3)
    k_gemm_tc<FD, false, true><<<GB, 256>>>(D, W3, nullptr, B, NN);
    CONVH(Ebuf, B, b3);                                 // Ebuf = embed2

    // u = embed3 @ Wd0 ; score = sigmoid(<u, embed2>)
    k_gemm_tc<FD, false, false><<<GB, 256>>>(C, Wd, nullptr, B, NN);  // B = u (keep)
    k_rowdot<<<nb((long)NN * 32, T), T>>>(out, (const float4*)B, (const float4*)Ebuf, 10, NN);

    // permuted path: (x@W1)[perm]
    k_gather<<<nb((long)NN * 32, T), T>>>((float4*)Ebuf, (const float4*)A, perm, NN);
    CONV1(A, Ebuf, b1);
    k_gemm_tc<FD, false, true><<<GB, 256>>>(A, W2, nullptr, Ebuf, NN);
    CONV1(A, Ebuf, b2);                                 // relu(A) = embed1_bad
    k_gemm_tc<FD, false, true><<<GB, 256>>>(A, W3, nullptr, Ebuf, NN);
    CONVH(A, Ebuf, b3);                                 // A = embed2_bad
    k_rowdot<<<nb((long)NN * 32, T), T>>>(out, (const float4*)B, (const float4*)A, 11, NN);

    // classifier: out[:,0:10] = conv(relu(D) @ Wc) + bc
    k_gemm_wc<<<nb((long)NN * NC, T), T>>>(F, D, Wc, NN);
    k_conv_csr_nc<<<nb((long)NN * 32, T), T>>>(out, F, start1, edge1, inv1, bc);

    #undef CONV1
    #undef CONVH
}

// round 17
// speedup vs baseline: 2.6479x; 1.0966x over previous
#include <cuda_runtime.h>
#include <cuda_bf16.h>
#include <math.h>
#include <stdint.h>

#define NN 100000
#define NE 1600000
#define NF 512
#define FD 128
#define NC 10

#define SCAN_B 512
#define SCAN_NBLK ((NN + SCAN_B - 1) / SCAN_B)

// ---------------- device scratch (static, no allocs) ----------------
__device__ __align__(16) float g_A[NN * FD];
__device__ __align__(16) float g_B[NN * FD];
__device__ __align__(16) float g_C[NN * FD];
__device__ __align__(16) float g_D[NN * FD];
__device__ __align__(16) float g_E[NN * FD];
__device__ __align__(16) float g_P[NN * FD];
__device__ __align__(16) float g_Q[NN * FD];
__device__ __align__(16) float g_F[NN * NC];
__device__ int   g_cnt1[NN], g_cnth[NN];
__device__ int   g_cur1[NN], g_curh[NN];
__device__ int   g_start1[NN + 1], g_starth[NN + 1];
__device__ int   g_part[SCAN_NBLK];
__device__ float g_inv1[NN], g_dis1[NN], g_invh[NN], g_dish[NN];
__device__ __align__(8) int2 g_edge1[NE], g_edgeh[NE];   // (src, weight-bits)

// ---------------- degree / CSR build ----------------
__global__ void k_zero(int* a, int* b, int* c, int* d, int n) {
    int i = blockIdx.x * blockDim.x + threadIdx.x;
    if (i < n) { a[i] = 0; b[i] = 0; c[i] = 0; d[i] = 0; }
}

__global__ void k_count(const int* __restrict__ d1, const int* __restrict__ dh,
                        int* cnt1, int* cnth, int e) {
    int i = blockIdx.x * blockDim.x + threadIdx.x;
    if (i < e) {
        atomicAdd(&cnt1[d1[i]], 1);
        atomicAdd(&cnth[dh[i]], 1);
    }
}

__global__ void k_finish(const int* __restrict__ cnt1, const int* __restrict__ cnth,
                         float* inv1, float* dis1, float* invh, float* dish, int n) {
    int i = blockIdx.x * blockDim.x + threadIdx.x;
    if (i < n) {
        float d = (float)cnt1[i] + 1.0f;
        inv1[i] = 1.0f / d;
        dis1[i] = rsqrtf(d);
        float dh = (float)cnth[i] + 1.0f;
        invh[i] = 1.0f / dh;
        dish[i] = rsqrtf(dh);
    }
}

__global__ void k_scan1(const int* __restrict__ cnt, int* part, int n) {
    __shared__ int sh[SCAN_B];
    int i = blockIdx.x * SCAN_B + threadIdx.x;
    sh[threadIdx.x] = (i < n) ? cnt[i] : 0;
    __syncthreads();
    for (int off = SCAN_B / 2; off > 0; off >>= 1) {
        if (threadIdx.x < off) sh[threadIdx.x] += sh[threadIdx.x + off];
        __syncthreads();
    }
    if (threadIdx.x == 0) part[blockIdx.x] = sh[0];
}

__global__ void k_scan2(int* part, int nblk) {
    if (threadIdx.x == 0 && blockIdx.x == 0) {
        int run = 0;
        for (int b = 0; b < nblk; b++) { int v = part[b]; part[b] = run; run += v; }
    }
}

__global__ void k_scan3(const int* __restrict__ cnt, const int* __restrict__ part,
                        int* start, int n) {
    __shared__ int sh[SCAN_B];
    int i = blockIdx.x * SCAN_B + threadIdx.x;
    int v = (i < n) ? cnt[i] : 0;
    sh[threadIdx.x] = v;
    __syncthreads();
    for (int off = 1; off < SCAN_B; off <<= 1) {
        int t = (threadIdx.x >= off) ? sh[threadIdx.x - off] : 0;
        __syncthreads();
        sh[threadIdx.x] += t;
        __syncthreads();
    }
    if (i < n) {
        int excl = sh[threadIdx.x] - v + part[blockIdx.x];
        start[i] = excl;
        if (i == n - 1) start[n] = excl + v;
    }
}

__global__ void k_fill(const int* __restrict__ src, const int* __restrict__ dst,
                       const int* __restrict__ start, int* cur,
                       const float* __restrict__ dis,
                       int2* __restrict__ edges, int e) {
    int i = blockIdx.x * blockDim.x + threadIdx.x;
    if (i >= e) return;
    int s = src[i], d = dst[i];
    int pos = start[d] + atomicAdd(&cur[d], 1);
    edges[pos] = make_int2(s, __float_as_int(dis[s] * dis[d]));
}

// ---------------- CSR GCN conv: warp per node, 128 features ----------------
__global__ void __launch_bounds__(256) k_conv_csr(
    float4* __restrict__ out, const float4* __restrict__ in,
    const int* __restrict__ start, const int2* __restrict__ edges,
    const float* __restrict__ inv, const float* __restrict__ bias) {
    int gid = blockIdx.x * blockDim.x + threadIdx.x;
    int node = gid >> 5, lane = gid & 31;
    if (node >= NN) return;
    int e0 = start[node], e1 = start[node + 1];
    float iv = inv[node];
    float4 b = ((const float4*)bias)[lane];
    float4 v = in[(size_t)node * 32 + lane];
    float ax = fmaf(v.x, iv, b.x), ay = fmaf(v.y, iv, b.y);
    float az = fmaf(v.z, iv, b.z), aw = fmaf(v.w, iv, b.w);
    #pragma unroll 4
    for (int e = e0; e < e1; e++) {
        int2 ed = __ldg(&edges[e]);
        float w = __int_as_float(ed.y);
        float4 u = __ldg(in + (size_t)ed.x * 32 + lane);
        ax = fmaf(u.x, w, ax); ay = fmaf(u.y, w, ay);
        az = fmaf(u.z, w, az); aw = fmaf(u.w, w, aw);
    }
    out[(size_t)node * 32 + lane] = make_float4(ax, ay, az, aw);
}

// classifier conv: warp per node, 10 features, writes out[:,0:10]
__global__ void __launch_bounds__(256) k_conv_csr_nc(
    float* __restrict__ out, const float* __restrict__ F,
    const int* __restrict__ start, const int2* __restrict__ edges,
    const float* __restrict__ inv, const float* __restrict__ bc) {
    int gid = blockIdx.x * blockDim.x + threadIdx.x;
    int node = gid >> 5, lane = gid & 31;
    if (node >= NN) return;
    int e0 = start[node], e1 = start[node + 1];
    float acc = 0.0f;
    if (lane < NC)
        acc = fmaf(F[(size_t)node * NC + lane], inv[node], bc[lane]);
    #pragma unroll 4
    for (int e = e0; e < e1; e++) {
        int2 ed = __ldg(&edges[e]);
        float w = __int_as_float(ed.y);
        if (lane < NC) acc = fmaf(__ldg(&F[(size_t)ed.x * NC + lane]), w, acc);
    }
    if (lane < NC) out[(size_t)node * 12 + lane] = acc;
}

__global__ void k_gather(float4* __restrict__ out, const float4* __restrict__ in,
                         const int* __restrict__ perm, int n) {
    int idx = blockIdx.x * blockDim.x + threadIdx.x;
    if (idx >= n * 32) return;
    int i = idx >> 5, q = idx & 31;
    out[idx] = in[(size_t)perm[i] * 32 + q];
}

// ---------------- tensor-core GEMM (bf16 3-MMA split, 2-stage pipeline) ----------------
__device__ __forceinline__ uint32_t pack_bf2(__nv_bfloat16 a, __nv_bfloat16 b) {
    __nv_bfloat162 t = __nv_bfloat162(a, b);
    return *reinterpret_cast<uint32_t*>(&t);
}

__device__ __forceinline__ void split2(float x, float y, uint32_t& hi, uint32_t& lo) {
    __nv_bfloat16 h0 = __float2bfloat16_rn(x);
    __nv_bfloat16 h1 = __float2bfloat16_rn(y);
    float r0 = x - __bfloat162float(h0);
    float r1 = y - __bfloat162float(h1);
    hi = pack_bf2(h0, h1);
    lo = pack_bf2(__float2bfloat16_rn(r0), __float2bfloat16_rn(r1));
}

__device__ __forceinline__ void mma_bf16(float* c, uint32_t a0, uint32_t a1,
                                         uint32_t a2, uint32_t a3,
                                         uint32_t b0, uint32_t b1) {
    asm volatile(
        "mma.sync.aligned.m16n8k16.row.col.f32.bf16.bf16.f32 "
        "{%0,%1,%2,%3}, {%4,%5,%6,%7}, {%8,%9}, {%0,%1,%2,%3};"
        : "+f"(c[0]), "+f"(c[1]), "+f"(c[2]), "+f"(c[3])
        : "r"(a0), "r"(a1), "r"(a2), "r"(a3), "r"(b0), "r"(b1));
}

#define SMS 136   // smem row stride (words), conflict-free for fragment reads

template <int K, bool BIAS, bool RELUIN>
__global__ void __launch_bounds__(256) k_gemm_tc(const float* __restrict__ A,
                                                 const float* __restrict__ W,
                                                 const float* __restrict__ bias,
                                                 float* __restrict__ C, int n) {
    __shared__ uint32_t sAh[2][8][SMS], sAl[2][8][SMS], sBh[2][8][SMS], sBl[2][8][SMS];
    const int tid = threadIdx.x;
    const int lane = tid & 31;
    const int wrp = tid >> 5;
    const int mw = (wrp & 3) * 32;
    const int nwb = (wrp >> 2) * 64;
    const int r = lane >> 2;
    const int q = lane & 3;
    const int m0 = blockIdx.x * 128;

    float acc[2][8][4];
    #pragma unroll
    for (int mi = 0; mi < 2; mi++)
        #pragma unroll
        for (int ni = 0; ni < 8; ni++)
            #pragma unroll
            for (int j = 0; j < 4; j++) acc[mi][ni][j] = 0.0f;

    const int lm = tid >> 1;
    const int lhalf = tid & 1;
    const int lnn = tid & 127;
    const int lp = tid >> 7;
    const bool valid = (m0 + lm) < n;

    float4 pa[2];
    float pw0[4], pw1[4];

    auto fetch = [&](int k0) {
        const float* arow = A + (size_t)(m0 + lm) * K + k0 + lhalf * 8;
        #pragma unroll
        for (int j = 0; j < 2; j++) {
            float4 v = make_float4(0.f, 0.f, 0.f, 0.f);
            if (valid) v = *(const float4*)(arow + j * 4);
            pa[j] = v;
        }
        #pragma unroll
        for (int qq = 0; qq < 4; qq++) {
            int kq = lp * 4 + qq;
            pw0[qq] = __ldg(&W[(size_t)(k0 + 2 * kq) * 128 + lnn]);
            pw1[qq] = __ldg(&W[(size_t)(k0 + 2 * kq + 1) * 128 + lnn]);
        }
    };

    auto stash = [&](int st) {
        #pragma unroll
        for (int j = 0; j < 2; j++) {
            float4 v = pa[j];
            if (RELUIN) {
                v.x = fmaxf(v.x, 0.f); v.y = fmaxf(v.y, 0.f);
                v.z = fmaxf(v.z, 0.f); v.w = fmaxf(v.w, 0.f);
            }
            int kq = lhalf * 4 + j * 2;
            uint32_t hi, lo;
            split2(v.x, v.y, hi, lo);
            sAh[st][kq][lm] = hi; sAl[st][kq][lm] = lo;
            split2(v.z, v.w, hi, lo);
            sAh[st][kq + 1][lm] = hi; sAl[st][kq + 1][lm] = lo;
        }
        #pragma unroll
        for (int qq = 0; qq < 4; qq++) {
            int kq = lp * 4 + qq;
            uint32_t hi, lo;
            split2(pw0[qq], pw1[qq], hi, lo);
            sBh[st][kq][lnn] = hi; sBl[st][kq][lnn] = lo;
        }
    };

    auto domma = [&](int st) {
        uint32_t bh[8][2], bl[8][2];
        #pragma unroll
        for (int ni = 0; ni < 8; ni++) {
            int nc = nwb + ni * 8 + r;
            bh[ni][0] = sBh[st][q][nc];     bh[ni][1] = sBh[st][q + 4][nc];
            bl[ni][0] = sBl[st][q][nc];     bl[ni][1] = sBl[st][q + 4][nc];
        }
        #pragma unroll
        for (int mi = 0; mi < 2; mi++) {
            int mb = mw + mi * 16;
            uint32_t ah0 = sAh[st][q][mb + r],     ah1 = sAh[st][q][mb + r + 8];
            uint32_t ah2 = sAh[st][q + 4][mb + r], ah3 = sAh[st][q + 4][mb + r + 8];
            uint32_t al0 = sAl[st][q][mb + r],     al1 = sAl[st][q][mb + r + 8];
            uint32_t al2 = sAl[st][q + 4][mb + r], al3 = sAl[st][q + 4][mb + r + 8];
            #pragma unroll
            for (int ni = 0; ni < 8; ni++) {
                mma_bf16(acc[mi][ni], ah0, ah1, ah2, ah3, bh[ni][0], bh[ni][1]);
                mma_bf16(acc[mi][ni], ah0, ah1, ah2, ah3, bl[ni][0], bl[ni][1]);
                mma_bf16(acc[mi][ni], al0, al1, al2, al3, bh[ni][0], bh[ni][1]);
            }
        }
    };

    fetch(0);
    stash(0);
    __syncthreads();
    int stage = 0;
    for (int k0 = 16; k0 < K; k0 += 16) {
        fetch(k0);
        domma(stage);
        stash(stage ^ 1);
        __syncthreads();
        stage ^= 1;
    }
    domma(stage);

    // ---- epilogue ----
    #pragma unroll
    for (int mi = 0; mi < 2; mi++) {
        #pragma unroll
        for (int ni = 0; ni < 8; ni++) {
            int row = m0 + mw + mi * 16 + r;
            int col = nwb + ni * 8 + q * 2;
            float b0 = BIAS ? bias[col] : 0.0f;
            float b1 = BIAS ? bias[col + 1] : 0.0f;
            if (row < n)
                *(float2*)&C[(size_t)row * 128 + col] =
                    make_float2(acc[mi][ni][0] + b0, acc[mi][ni][1] + b1);
            if (row + 8 < n)
                *(float2*)&C[(size_t)(row + 8) * 128 + col] =
                    make_float2(acc[mi][ni][2] + b0, acc[mi][ni][3] + b1);
        }
    }
}

// ---------------- bilinear score ----------------
__global__ void k_rowdot(float* __restrict__ out, const float4* __restrict__ u,
                         const float4* __restrict__ v, int col, int n) {
    int gid = blockIdx.x * blockDim.x + threadIdx.x;
    int i = gid >> 5, lane = gid & 31;
    if (i >= n) return;
    float4 a = u[(size_t)i * 32 + lane];
    float4 b = v[(size_t)i * 32 + lane];
    float s = a.x * b.x + a.y * b.y + a.z * b.z + a.w * b.w;
    #pragma unroll
    for (int off = 16; off > 0; off >>= 1)
        s += __shfl_down_sync(0xffffffffu, s, off);
    if (lane == 0) out[(size_t)i * 12 + col] = 1.0f / (1.0f + expf(-s));
}

// ---------------- classifier pre-GEMM: F[n,10] = relu(D) @ Wc ----------------
__global__ void k_gemm_wc(float* __restrict__ F, const float* __restrict__ D,
                          const float* __restrict__ Wc, int n) {
    __shared__ float wcs[FD * NC];
    for (int t = threadIdx.x; t < FD * NC; t += blockDim.x) wcs[t] = Wc[t];
    __syncthreads();
    int gid = blockIdx.x * blockDim.x + threadIdx.x;
    if (gid >= n * NC) return;
    int i = gid / NC, j = gid % NC;
    const float* drow = &D[(size_t)i * FD];
    float s = 0.0f;
    #pragma unroll
    for (int k = 0; k < FD; k++)
        s = fmaf(fmaxf(__ldg(&drow[k]), 0.0f), wcs[k * NC + j], s);
    F[gid] = s;
}

// ---------------- launch ----------------
static inline int nb(long total, int tpb) { return (int)((total + tpb - 1) / tpb); }

extern "C" void kernel_launch(void* const* d_in, const int* in_sizes, int n_in,
                              void* d_out, int out_size) {
    const float* x    = (const float*)d_in[0];
    const int*   e1   = (const int*)d_in[1];
    const int*   eh   = (const int*)d_in[2];
    const int*   perm = (const int*)d_in[4];
    const float* W1 = (const float*)d_in[5];
    const float* b1 = (const float*)d_in[6];
    const float* W2 = (const float*)d_in[7];
    const float* b2 = (const float*)d_in[8];
    const float* W3 = (const float*)d_in[9];
    const float* b3 = (const float*)d_in[10];
    const float* M1 = (const float*)d_in[11];
    const float* mb1 = (const float*)d_in[12];
    const float* M2 = (const float*)d_in[13];
    const float* mb2 = (const float*)d_in[14];
    const float* Wc = (const float*)d_in[15];
    const float* bc = (const float*)d_in[16];
    const float* Wd = (const float*)d_in[17];
    float* out = (float*)d_out;

    const int* src1 = e1;       const int* dst1 = e1 + NE;
    const int* srch = eh;       const int* dsth = eh + NE;

    float *A, *B, *C, *D, *Ebuf, *P, *Q, *F;
    float *inv1, *dis1, *invh, *dish;
    int *cnt1, *cnth, *cur1, *curh, *start1, *starth, *part;
    int2 *edge1, *edgeh;
    cudaGetSymbolAddress((void**)&A, g_A);
    cudaGetSymbolAddress((void**)&B, g_B);
    cudaGetSymbolAddress((void**)&C, g_C);
    cudaGetSymbolAddress((void**)&D, g_D);
    cudaGetSymbolAddress((void**)&Ebuf, g_E);
    cudaGetSymbolAddress((void**)&P, g_P);
    cudaGetSymbolAddress((void**)&Q, g_Q);
    cudaGetSymbolAddress((void**)&F, g_F);
    cudaGetSymbolAddress((void**)&cnt1, g_cnt1);
    cudaGetSymbolAddress((void**)&cnth, g_cnth);
    cudaGetSymbolAddress((void**)&cur1, g_cur1);
    cudaGetSymbolAddress((void**)&curh, g_curh);
    cudaGetSymbolAddress((void**)&start1, g_start1);
    cudaGetSymbolAddress((void**)&starth, g_starth);
    cudaGetSymbolAddress((void**)&part, g_part);
    cudaGetSymbolAddress((void**)&inv1, g_inv1);
    cudaGetSymbolAddress((void**)&dis1, g_dis1);
    cudaGetSymbolAddress((void**)&invh, g_invh);
    cudaGetSymbolAddress((void**)&dish, g_dish);
    cudaGetSymbolAddress((void**)&edge1, g_edge1);
    cudaGetSymbolAddress((void**)&edgeh, g_edgeh);

    // Side stream + events: created once on the first (uncaptured) correctness
    // call; reused by the capture call. No device memory is allocated.
    static cudaStream_t s2 = nullptr;
    static cudaEvent_t evFork = nullptr, evH1 = nullptr, evFork2 = nullptr, evPerm = nullptr;
    if (s2 == nullptr) {
        cudaStreamCreateWithFlags(&s2, cudaStreamNonBlocking);
        cudaEventCreateWithFlags(&evFork,  cudaEventDisableTiming);
        cudaEventCreateWithFlags(&evH1,    cudaEventDisableTiming);
        cudaEventCreateWithFlags(&evFork2, cudaEventDisableTiming);
        cudaEventCreateWithFlags(&evPerm,  cudaEventDisableTiming);
    }

    const int T = 256;
    const int GB = nb(NN, 128);

    // ---- fork: h1 = x @ W1 on s2, CSR build on stream 0 ----
    cudaEventRecord(evFork, 0);
    cudaStreamWaitEvent(s2, evFork, 0);
    k_gemm_tc<NF, false, false><<<GB, 256, 0, s2>>>(x, W1, nullptr, A, NN);
    cudaEventRecord(evH1, s2);

    k_zero<<<nb(NN, T), T>>>(cnt1, cnth, cur1, curh, NN);
    k_count<<<nb(NE, T), T>>>(dst1, dsth, cnt1, cnth, NE);
    k_finish<<<nb(NN, T), T>>>(cnt1, cnth, inv1, dis1, invh, dish, NN);
    k_scan1<<<SCAN_NBLK, SCAN_B>>>(cnt1, part, NN);
    k_scan2<<<1, 32>>>(part, SCAN_NBLK);
    k_scan3<<<SCAN_NBLK, SCAN_B>>>(cnt1, part, start1, NN);
    k_scan1<<<SCAN_NBLK, SCAN_B>>>(cnth, part, NN);
    k_scan2<<<1, 32>>>(part, SCAN_NBLK);
    k_scan3<<<SCAN_NBLK, SCAN_B>>>(cnth, part, starth, NN);
    k_fill<<<nb(NE, T), T>>>(src1, dst1, start1, cur1, dis1, edge1, NE);
    k_fill<<<nb(NE, T), T>>>(srch, dsth, starth, curh, dish, edgeh, NE);

    // join h1 into stream 0; then fork the permuted chain onto s2
    cudaStreamWaitEvent(0, evH1, 0);
    cudaEventRecord(evFork2, 0);
    cudaStreamWaitEvent(s2, evFork2, 0);

    #define CONV1(OUT, IN, BIAS, ST) \
        k_conv_csr<<<nb((long)NN * 32, T), T, 0, (ST)>>>((float4*)(OUT), (const float4*)(IN), \
                                                start1, edge1, inv1, (BIAS));
    #define CONVH(OUT, IN, BIAS, ST) \
        k_conv_csr<<<nb((long)NN * 32, T), T, 0, (ST)>>>((float4*)(OUT), (const float4*)(IN), \
                                                starth, edgeh, invh, (BIAS));

    // ---- permuted chain on s2 (uses P/Q only; reads A, edge data) ----
    k_gather<<<nb((long)NN * 32, T), T, 0, s2>>>((float4*)P, (const float4*)A, perm, NN);
    CONV1(Q, P, b1, s2);
    k_gemm_tc<FD, false, true><<<GB, 256, 0, s2>>>(Q, W2, nullptr, P, NN);
    CONV1(Q, P, b2, s2);                                // relu(Q) = embed1_bad
    k_gemm_tc<FD, false, true><<<GB, 256, 0, s2>>>(Q, W3, nullptr, P, NN);
    CONVH(Q, P, b3, s2);                                // Q = embed2_bad
    cudaEventRecord(evPerm, s2);

    // ---- main chain on stream 0 ----
    CONV1(B, A, b1, 0);
    k_gemm_tc<FD, false, true><<<GB, 256>>>(B, W2, nullptr, C, NN);
    CONV1(D, C, b2, 0);                                 // relu(D) = embed1

    k_gemm_tc<FD, true, true><<<GB, 256>>>(D, M1, mb1, B, NN);
    k_gemm_tc<FD, true, true><<<GB, 256>>>(B, M2, mb2, C, NN);   // C = embed3

    k_gemm_tc<FD, false, true><<<GB, 256>>>(D, W3, nullptr, B, NN);
    CONVH(Ebuf, B, b3, 0);                              // Ebuf = embed2

    k_gemm_tc<FD, false, false><<<GB, 256>>>(C, Wd, nullptr, B, NN);  // B = u (keep)
    k_rowdot<<<nb((long)NN * 32, T), T>>>(out, (const float4*)B, (const float4*)Ebuf, 10, NN);

    // classifier: out[:,0:10] = conv(relu(D) @ Wc) + bc
    k_gemm_wc<<<nb((long)NN * NC, T), T>>>(F, D, Wc, NN);
    k_conv_csr_nc<<<nb((long)NN * 32, T), T>>>(out, F, start1, edge1, inv1, bc);

    // ---- join permuted chain, final score ----
    cudaStreamWaitEvent(0, evPerm, 0);
    k_rowdot<<<nb((long)NN * 32, T), T>>>(out, (const float4*)B, (const float4*)Q, 11, NN);

    #undef CONV1
    #undef CONVH
}